// round 11
// baseline (speedup 1.0000x reference)
#include <cuda_runtime.h>
#include <math.h>

#define SEQ   2048
#define SEQ2  (SEQ / 2)
#define SEQ4  (SEQ / 4)
#define SEQ8  (SEQ / 8)       // 256 blocked-8 steps
#define EMB   1024
#define HID   2048
#define VOCAB 50257
#define WSTRIDE (EMB + HID)   // 3072, row stride of W_i2h

#define NCTA 128
#define NREP 4

// ---------------- scratch (device globals: allocation-free rule) ----------
__device__ __align__(16) float g_X [SEQ  * HID];
__device__ __align__(16) float g_X2[SEQ2 * HID];
__device__ __align__(16) float g_X4[SEQ4 * HID];
__device__ __align__(16) float g_X8[SEQ8 * HID];
__device__ __align__(16) float g_W2[HID * HID];
__device__ __align__(16) float g_W4[HID * HID];
__device__ __align__(16) float g_W8[HID * HID];
__device__ __align__(16) float g_hrep[2][NREP][HID];
__device__ unsigned g_cnt;
__device__ int g_tok64 = 0;

// ---------------- memory-order / packed-math helpers ----------------------
__device__ __forceinline__ unsigned ld_relaxed(const unsigned* p) {
    unsigned v;
    asm volatile("ld.relaxed.gpu.global.u32 %0, [%1];" : "=r"(v) : "l"(p) : "memory");
    return v;
}
__device__ __forceinline__ void red_add_release(unsigned* p, unsigned v) {
    asm volatile("red.release.gpu.global.add.u32 [%0], %1;" :: "l"(p), "r"(v) : "memory");
}
__device__ __forceinline__ void fence_acq() {
    asm volatile("fence.acq_rel.gpu;" ::: "memory");
}
__device__ __forceinline__ unsigned long long pack2(float lo, float hi) {
    unsigned long long r;
    asm("mov.b64 %0, {%1, %2};" : "=l"(r) : "f"(lo), "f"(hi));
    return r;
}
__device__ __forceinline__ void unpack2(float& lo, float& hi, unsigned long long v) {
    asm("mov.b64 {%0, %1}, %2;" : "=f"(lo), "=f"(hi) : "l"(v));
}
__device__ __forceinline__ void ffma2(unsigned long long& acc,
                                      unsigned long long a, unsigned long long b) {
    asm("fma.rn.f32x2 %0, %1, %2, %0;" : "+l"(acc) : "l"(a), "l"(b));
}

// ---------------- per-launch reset ----------------------------------------
__global__ void reset_kernel() {
    if (threadIdx.x == 0) g_cnt = 0;
}

// ---------------- token dtype detection -----------------------------------
__global__ void detect_tok_kernel(const int* __restrict__ p) {
    __shared__ int bad;
    if (threadIdx.x == 0) bad = 0;
    __syncthreads();
    int mybad = 0;
    for (int i = threadIdx.x; i < SEQ / 2; i += blockDim.x) {
        int lo = p[2 * i];
        int hi = p[2 * i + 1];
        if (hi != 0 || lo < 0 || lo >= VOCAB) mybad = 1;
    }
    if (mybad) atomicOr(&bad, 1);
    __syncthreads();
    if (threadIdx.x == 0) g_tok64 = bad ? 0 : 1;
}

// =================== GEMM tiles: 128x128x16, 256 thr, 8x8 micro ==========
#define BM 128
#define BN 128
#define BK 16
#define GTHREADS 256
#define BN2 (2 * BN + 8)      // duplicated-B row width (floats)

// Packed-f32x2 micro-kernel: a-pairs and duplicated-b pairs read directly as
// u64 from SMEM (no pack MOVs). acc2[ip][j]: .lo = row 2ip, .hi = row 2ip+1.
__device__ __forceinline__ void micro_ffma2(
    const float (*As)[BM + 4], const float (*Bs2)[BN2],
    int ty, int tx, unsigned long long acc2[4][8]) {
#pragma unroll
    for (int k = 0; k < BK; k++) {
        ulonglong2 a01 = *(const ulonglong2*)&As[k][ty * 8];
        ulonglong2 a23 = *(const ulonglong2*)&As[k][ty * 8 + 4];
        unsigned long long ap[4] = {a01.x, a01.y, a23.x, a23.y};
        const ulonglong2* bp = (const ulonglong2*)&Bs2[k][tx * 16];
        ulonglong2 b01 = bp[0], b23 = bp[1], b45 = bp[2], b67 = bp[3];
        unsigned long long bb[8] = {b01.x, b01.y, b23.x, b23.y,
                                    b45.x, b45.y, b67.x, b67.y};
#pragma unroll
        for (int j = 0; j < 8; j++)
#pragma unroll
            for (int ip = 0; ip < 4; ip++)
                ffma2(acc2[ip][j], ap[ip], bb[j]);
    }
}

// ---------------- X = E @ W_e^T + b ---------------------------------------
__global__ void __launch_bounds__(GTHREADS, 2)
gemm_x_kernel(const int* __restrict__ toks,
              const float* __restrict__ emb,
              const float* __restrict__ Wi2h,
              const float* __restrict__ bias) {
    __shared__ __align__(16) float As[BK][BM + 4];
    __shared__ __align__(16) float Bs2[BK][BN2];
    __shared__ int stok[BM];

    const int tid = threadIdx.x;
    const int t0 = blockIdx.y * BM;
    const int r0 = blockIdx.x * BN;
    const int tok64 = g_tok64;

    if (tid < BM) {
        int t = t0 + tid;
        stok[tid] = tok64 ? toks[2 * t] : toks[t];
    }
    __syncthreads();

    const int tx = tid & 15;
    const int ty = tid >> 4;

    unsigned long long acc2[4][8];
#pragma unroll
    for (int ip = 0; ip < 4; ip++)
#pragma unroll
        for (int j = 0; j < 8; j++) acc2[ip][j] = 0ull;

    for (int kk = 0; kk < EMB; kk += BK) {
#pragma unroll
        for (int i = 0; i < 2; i++) {
            int v = tid + i * GTHREADS;
            int m = v >> 2;
            int k = (v & 3) << 2;
            float4 a = *(const float4*)&emb[(size_t)stok[m] * EMB + kk + k];
            As[k + 0][m] = a.x; As[k + 1][m] = a.y;
            As[k + 2][m] = a.z; As[k + 3][m] = a.w;
            // B[j=m][k..k+3] -> duplicated columns of Bs2
            float4 b = *(const float4*)&Wi2h[(size_t)(r0 + m) * WSTRIDE + kk + k];
            *(float2*)&Bs2[k + 0][2 * m] = make_float2(b.x, b.x);
            *(float2*)&Bs2[k + 1][2 * m] = make_float2(b.y, b.y);
            *(float2*)&Bs2[k + 2][2 * m] = make_float2(b.z, b.z);
            *(float2*)&Bs2[k + 3][2 * m] = make_float2(b.w, b.w);
        }
        __syncthreads();
        micro_ffma2(As, Bs2, ty, tx, acc2);
        __syncthreads();
    }

    float bv[8];
#pragma unroll
    for (int j = 0; j < 8; j++) bv[j] = bias[r0 + tx * 8 + j];

#pragma unroll
    for (int ip = 0; ip < 4; ip++) {
        float o0[8], o1[8];
#pragma unroll
        for (int j = 0; j < 8; j++) {
            float lo, hi;
            unpack2(lo, hi, acc2[ip][j]);
            o0[j] = lo + bv[j];
            o1[j] = hi + bv[j];
        }
        int trow0 = t0 + ty * 8 + 2 * ip;
        *(float4*)&g_X[(size_t)trow0 * HID + r0 + tx * 8]     = *(float4*)&o0[0];
        *(float4*)&g_X[(size_t)trow0 * HID + r0 + tx * 8 + 4] = *(float4*)&o0[4];
        *(float4*)&g_X[(size_t)(trow0 + 1) * HID + r0 + tx * 8]     = *(float4*)&o1[0];
        *(float4*)&g_X[(size_t)(trow0 + 1) * HID + r0 + tx * 8 + 4] = *(float4*)&o1[4];
    }
}

// ---------------- generic square product: C = A @ A ------------------------
template <int ASTRIDE, int AOFF>
__global__ void __launch_bounds__(GTHREADS, 2)
gemm_sq_kernel(const float* __restrict__ A, float* __restrict__ C) {
    __shared__ __align__(16) float As[BK][BM + 4];
    __shared__ __align__(16) float Bs2[BK][BN2];

    const int tid = threadIdx.x;
    const int i0 = blockIdx.y * BM;
    const int j0 = blockIdx.x * BN;

    const int tx = tid & 15;
    const int ty = tid >> 4;

    unsigned long long acc2[4][8];
#pragma unroll
    for (int ip = 0; ip < 4; ip++)
#pragma unroll
        for (int j = 0; j < 8; j++) acc2[ip][j] = 0ull;

    for (int kk = 0; kk < HID; kk += BK) {
#pragma unroll
        for (int i = 0; i < 2; i++) {
            int v = tid + i * GTHREADS;
            int m = v >> 2;
            int k = (v & 3) << 2;
            float4 a = *(const float4*)&A[(size_t)(i0 + m) * ASTRIDE + AOFF + kk + k];
            As[k + 0][m] = a.x; As[k + 1][m] = a.y;
            As[k + 2][m] = a.z; As[k + 3][m] = a.w;
        }
        // B tile: A[kk+k][j0+j], contiguous in j -> duplicate on store
#pragma unroll
        for (int i = 0; i < 2; i++) {
            int v = tid + i * GTHREADS;
            int k = v >> 5;
            int j = (v & 31) << 2;
            float4 b = *(const float4*)&A[(size_t)(kk + k) * ASTRIDE + AOFF + j0 + j];
            *(float2*)&Bs2[k][2 * j + 0] = make_float2(b.x, b.x);
            *(float2*)&Bs2[k][2 * j + 2] = make_float2(b.y, b.y);
            *(float2*)&Bs2[k][2 * j + 4] = make_float2(b.z, b.z);
            *(float2*)&Bs2[k][2 * j + 6] = make_float2(b.w, b.w);
        }
        __syncthreads();
        micro_ffma2(As, Bs2, ty, tx, acc2);
        __syncthreads();
    }

#pragma unroll
    for (int ip = 0; ip < 4; ip++) {
        float o0[8], o1[8];
#pragma unroll
        for (int j = 0; j < 8; j++) unpack2(o0[j], o1[j], acc2[ip][j]);
        int r = i0 + ty * 8 + 2 * ip;
        *(float4*)&C[(size_t)r * HID + j0 + tx * 8]     = *(float4*)&o0[0];
        *(float4*)&C[(size_t)r * HID + j0 + tx * 8 + 4] = *(float4*)&o0[4];
        *(float4*)&C[(size_t)(r + 1) * HID + j0 + tx * 8]     = *(float4*)&o1[0];
        *(float4*)&C[(size_t)(r + 1) * HID + j0 + tx * 8 + 4] = *(float4*)&o1[4];
    }
}

// ---------------- fold: Y[s] = W @ Xin[2s] + Xin[2s+1] ---------------------
template <int WSTRIDE_, int WOFF>
__global__ void __launch_bounds__(GTHREADS, 2)
gemm_fold_kernel(const float* __restrict__ W,
                 const float* __restrict__ Xin,
                 float* __restrict__ Y) {
    __shared__ __align__(16) float As[BK][BM + 4];
    __shared__ __align__(16) float Bs2[BK][BN2];

    const int tid = threadIdx.x;
    const int s0 = blockIdx.y * BM;
    const int r0 = blockIdx.x * BN;

    const int tx = tid & 15;
    const int ty = tid >> 4;

    unsigned long long acc2[4][8];
#pragma unroll
    for (int ip = 0; ip < 4; ip++)
#pragma unroll
        for (int j = 0; j < 8; j++) acc2[ip][j] = 0ull;

    for (int kk = 0; kk < HID; kk += BK) {
#pragma unroll
        for (int i = 0; i < 2; i++) {
            int v = tid + i * GTHREADS;
            int m = v >> 2;
            int k = (v & 3) << 2;
            float4 a = *(const float4*)&Xin[(size_t)(2 * (s0 + m)) * HID + kk + k];
            As[k + 0][m] = a.x; As[k + 1][m] = a.y;
            As[k + 2][m] = a.z; As[k + 3][m] = a.w;
            // B[j=m][k..k+3] = W[r0+m][kk+k..] -> duplicated columns
            float4 b = *(const float4*)&W[(size_t)(r0 + m) * WSTRIDE_ + WOFF + kk + k];
            *(float2*)&Bs2[k + 0][2 * m] = make_float2(b.x, b.x);
            *(float2*)&Bs2[k + 1][2 * m] = make_float2(b.y, b.y);
            *(float2*)&Bs2[k + 2][2 * m] = make_float2(b.z, b.z);
            *(float2*)&Bs2[k + 3][2 * m] = make_float2(b.w, b.w);
        }
        __syncthreads();
        micro_ffma2(As, Bs2, ty, tx, acc2);
        __syncthreads();
    }

#pragma unroll
    for (int ip = 0; ip < 4; ip++) {
        int s = s0 + ty * 8 + 2 * ip;
#pragma unroll
        for (int half = 0; half < 2; half++) {
            int ss = s + half;
            float4 e0 = *(const float4*)&Xin[(size_t)(2 * ss + 1) * HID + r0 + tx * 8];
            float4 e1 = *(const float4*)&Xin[(size_t)(2 * ss + 1) * HID + r0 + tx * 8 + 4];
            float o[8];
#pragma unroll
            for (int j = 0; j < 8; j++) {
                float lo, hi;
                unpack2(lo, hi, acc2[ip][j]);
                o[j] = (half == 0 ? lo : hi);
            }
            o[0] += e0.x; o[1] += e0.y; o[2] += e0.z; o[3] += e0.w;
            o[4] += e1.x; o[5] += e1.y; o[6] += e1.z; o[7] += e1.w;
            *(float4*)&Y[(size_t)ss * HID + r0 + tx * 8]     = *(float4*)&o[0];
            *(float4*)&Y[(size_t)ss * HID + r0 + tx * 8 + 4] = *(float4*)&o[4];
        }
    }
}

// ---------------- persistent recurrence kernel (256 steps, W8/X8) ---------
#define ROWS_PER_CTA (HID / NCTA)  // 16
#define RTHREADS 512

__global__ void __launch_bounds__(RTHREADS, 1)
rnn_kernel(const float* __restrict__ Wh2o,
           const float* __restrict__ bh2o,
           float* __restrict__ out) {
    __shared__ __align__(16) float sh[HID];
    __shared__ float sred[64];

    const int tid = threadIdx.x;
    const int cta = blockIdx.x;
    const int r0  = cta * ROWS_PER_CTA;
    const int repl = cta & (NREP - 1);

    const int w = tid >> 5, l = tid & 31;
    const int grp = w & 3;
    const int q   = w >> 2;

    unsigned long long Wr[4][8];
#pragma unroll
    for (int rr = 0; rr < 4; rr++)
#pragma unroll
        for (int k = 0; k < 4; k++) {
            float4 wv = *(const float4*)&g_W8[
                (size_t)(r0 + 4 * grp + rr) * HID
                + (q << 9) + (l << 2) + (k << 7)];
            Wr[rr][2 * k]     = pack2(wv.x, wv.y);
            Wr[rr][2 * k + 1] = pack2(wv.z, wv.w);
        }

    for (int t = 0; t < SEQ8; t++) {
        float xv = 0.f;
        if (tid < ROWS_PER_CTA) xv = __ldcg(&g_X8[(size_t)t * HID + r0 + tid]);

        if (t > 0) {
            if (w == 0) {
                const unsigned tgt = (unsigned)t << 7;
                unsigned e;
                do { e = ld_relaxed(&g_cnt); }
                while (__any_sync(0xffffffffu, e < tgt));
                fence_acq();
            }
            __syncthreads();

            const float* hprev = g_hrep[(t - 1) & 1][repl];
            float4 ch = __ldcg((const float4*)&hprev[(w << 7) + (l << 2)]);
            *(float4*)&sh[(w << 7) + (l << 2)] = ch;
            __syncthreads();

            const float4* sh4 = (const float4*)sh;
            unsigned long long acc2[4];
#pragma unroll
            for (int rr = 0; rr < 4; rr++) acc2[rr] = 0ull;

#pragma unroll
            for (int k = 0; k < 4; k++) {
                float4 hv = sh4[(q << 7) + (k << 5) + l];
                unsigned long long h0 = pack2(hv.x, hv.y);
                unsigned long long h1 = pack2(hv.z, hv.w);
#pragma unroll
                for (int rr = 0; rr < 4; rr++) {
                    ffma2(acc2[rr], Wr[rr][2 * k],     h0);
                    ffma2(acc2[rr], Wr[rr][2 * k + 1], h1);
                }
            }

#pragma unroll
            for (int rr = 0; rr < 4; rr++) {
                float lo, hi;
                unpack2(lo, hi, acc2[rr]);
                float v = lo + hi;
                v += __shfl_xor_sync(0xffffffffu, v, 16);
                v += __shfl_xor_sync(0xffffffffu, v, 8);
                v += __shfl_xor_sync(0xffffffffu, v, 4);
                v += __shfl_xor_sync(0xffffffffu, v, 2);
                v += __shfl_xor_sync(0xffffffffu, v, 1);
                if (l == 0) sred[w * 4 + rr] = v;
            }
            __syncthreads();

            if (tid < ROWS_PER_CTA) {
                int g = tid >> 2, rr = tid & 3;
                float v = xv;
#pragma unroll
                for (int qq = 0; qq < 4; qq++)
                    v += sred[((qq << 2) | g) * 4 + rr];
#pragma unroll
                for (int r = 0; r < NREP; r++)
                    g_hrep[t & 1][r][r0 + tid] = v;
            }
        } else {
            if (tid < ROWS_PER_CTA) {
#pragma unroll
                for (int r = 0; r < NREP; r++)
                    g_hrep[0][r][r0 + tid] = xv;
            }
        }

        if (w == 0) {
            __syncwarp();
            if (l == 0) red_add_release(&g_cnt, 1u);
        }
    }

    // readout
    if (cta == 0) {
        if (w == 0) {
            const unsigned tgt = (unsigned)SEQ8 << 7;
            unsigned e;
            do { e = ld_relaxed(&g_cnt); }
            while (__any_sync(0xffffffffu, e < tgt));
            fence_acq();
        }
        __syncthreads();
        const float* hf = g_hrep[(SEQ8 - 1) & 1][0];
        float s = 0.f;
        for (int j = tid; j < HID; j += RTHREADS) s += __ldcg(&hf[j]) * Wh2o[j];
#pragma unroll
        for (int o = 16; o > 0; o >>= 1) s += __shfl_xor_sync(0xffffffffu, s, o);
        __syncthreads();
        if (l == 0) sred[w] = s;
        __syncthreads();
        if (tid == 0) {
            float tot = 0.f;
#pragma unroll
            for (int i = 0; i < RTHREADS / 32; i++) tot += sred[i];
            tot += bh2o[0];
            out[0] = 1.f / (1.f + expf(-tot));
        }
    }
}

// ---------------- launch ---------------------------------------------------
extern "C" void kernel_launch(void* const* d_in, const int* in_sizes, int n_in,
                              void* d_out, int out_size) {
    const int*   toks = (const int*)d_in[0];
    const float* emb  = (const float*)d_in[1];
    const float* Wi2h = (const float*)d_in[2];
    const float* bi2h = (const float*)d_in[3];
    const float* Wh2o = (const float*)d_in[4];
    const float* bh2o = (const float*)d_in[5];
    float* out = (float*)d_out;

    float* gX;  cudaGetSymbolAddress((void**)&gX,  g_X);
    float* gX2; cudaGetSymbolAddress((void**)&gX2, g_X2);
    float* gX4; cudaGetSymbolAddress((void**)&gX4, g_X4);
    float* gX8; cudaGetSymbolAddress((void**)&gX8, g_X8);
    float* gW2; cudaGetSymbolAddress((void**)&gW2, g_W2);
    float* gW4; cudaGetSymbolAddress((void**)&gW4, g_W4);
    float* gW8; cudaGetSymbolAddress((void**)&gW8, g_W8);

    reset_kernel<<<1, 32>>>();
    detect_tok_kernel<<<1, 256>>>(toks);
    gemm_x_kernel<<<dim3(HID / BN, SEQ / BM), GTHREADS>>>(toks, emb, Wi2h, bi2h);
    gemm_sq_kernel<WSTRIDE, EMB><<<dim3(HID / BN, HID / BM), GTHREADS>>>(Wi2h, gW2);
    gemm_fold_kernel<WSTRIDE, EMB><<<dim3(HID / BN, SEQ2 / BM), GTHREADS>>>(Wi2h, gX, gX2);
    gemm_sq_kernel<HID, 0><<<dim3(HID / BN, HID / BM), GTHREADS>>>(gW2, gW4);
    gemm_fold_kernel<HID, 0><<<dim3(HID / BN, SEQ4 / BM), GTHREADS>>>(gW2, gX2, gX4);
    gemm_sq_kernel<HID, 0><<<dim3(HID / BN, HID / BM), GTHREADS>>>(gW4, gW8);
    gemm_fold_kernel<HID, 0><<<dim3(HID / BN, SEQ8 / BM), GTHREADS>>>(gW4, gX4, gX8);
    rnn_kernel<<<NCTA, RTHREADS>>>(Wh2o, bh2o, out);
}

// round 12
// speedup vs baseline: 2.4459x; 2.4459x over previous
#include <cuda_runtime.h>
#include <math.h>

#define SEQ   2048
#define SEQ2  (SEQ / 2)
#define SEQ4  (SEQ / 4)
#define SEQ8  (SEQ / 8)       // 256 blocked-8 steps
#define EMB   1024
#define HID   2048
#define VOCAB 50257
#define WSTRIDE (EMB + HID)   // 3072, row stride of W_i2h

#define NCTA 128
#define NREP 4

// ---------------- scratch (device globals: allocation-free rule) ----------
__device__ __align__(16) float g_X [SEQ  * HID];
__device__ __align__(16) float g_X2[SEQ2 * HID];
__device__ __align__(16) float g_X4[SEQ4 * HID];
__device__ __align__(16) float g_X8[SEQ8 * HID];
__device__ __align__(16) float g_W2[HID * HID];
__device__ __align__(16) float g_W4[HID * HID];
__device__ __align__(16) float g_W8[HID * HID];
__device__ __align__(16) float g_hrep[2][NREP][HID];
__device__ unsigned g_cnt;
__device__ int g_tok64 = 0;

// ---------------- memory-order / packed-math helpers ----------------------
__device__ __forceinline__ unsigned ld_relaxed(const unsigned* p) {
    unsigned v;
    asm volatile("ld.relaxed.gpu.global.u32 %0, [%1];" : "=r"(v) : "l"(p) : "memory");
    return v;
}
__device__ __forceinline__ void red_add_release(unsigned* p, unsigned v) {
    asm volatile("red.release.gpu.global.add.u32 [%0], %1;" :: "l"(p), "r"(v) : "memory");
}
__device__ __forceinline__ void fence_acq() {
    asm volatile("fence.acq_rel.gpu;" ::: "memory");
}
__device__ __forceinline__ unsigned long long pack2(float lo, float hi) {
    unsigned long long r;
    asm("mov.b64 %0, {%1, %2};" : "=l"(r) : "f"(lo), "f"(hi));
    return r;
}
__device__ __forceinline__ void unpack2(float& lo, float& hi, unsigned long long v) {
    asm("mov.b64 {%0, %1}, %2;" : "=f"(lo), "=f"(hi) : "l"(v));
}
__device__ __forceinline__ void ffma2(unsigned long long& acc,
                                      unsigned long long a, unsigned long long b) {
    asm("fma.rn.f32x2 %0, %1, %2, %0;" : "+l"(acc) : "l"(a), "l"(b));
}

// ---------------- per-launch reset ----------------------------------------
__global__ void reset_kernel() {
    if (threadIdx.x == 0) g_cnt = 0;
}

// ---------------- token dtype detection -----------------------------------
__global__ void detect_tok_kernel(const int* __restrict__ p) {
    __shared__ int bad;
    if (threadIdx.x == 0) bad = 0;
    __syncthreads();
    int mybad = 0;
    for (int i = threadIdx.x; i < SEQ / 2; i += blockDim.x) {
        int lo = p[2 * i];
        int hi = p[2 * i + 1];
        if (hi != 0 || lo < 0 || lo >= VOCAB) mybad = 1;
    }
    if (mybad) atomicOr(&bad, 1);
    __syncthreads();
    if (threadIdx.x == 0) g_tok64 = bad ? 0 : 1;
}

// =================== GEMM tiles: 128x128x16, 256 thr, 8x8 micro ==========
// (R9 plain-FFMA micro-kernel — proven 43 TF/s, regs 127, 2 CTA/SM.)
#define BM 128
#define BN 128
#define BK 16
#define GTHREADS 256

// ---------------- X = E @ W_e^T + b ---------------------------------------
__global__ void __launch_bounds__(GTHREADS, 1)
gemm_x_kernel(const int* __restrict__ toks,
              const float* __restrict__ emb,
              const float* __restrict__ Wi2h,
              const float* __restrict__ bias) {
    __shared__ __align__(16) float As[BK][BM + 4];
    __shared__ __align__(16) float Bs[BK][BN + 4];
    __shared__ int stok[BM];

    const int tid = threadIdx.x;
    const int t0 = blockIdx.y * BM;
    const int r0 = blockIdx.x * BN;
    const int tok64 = g_tok64;

    if (tid < BM) {
        int t = t0 + tid;
        stok[tid] = tok64 ? toks[2 * t] : toks[t];
    }
    __syncthreads();

    const int tx = tid & 15;
    const int ty = tid >> 4;

    float acc[8][8];
#pragma unroll
    for (int i = 0; i < 8; i++)
#pragma unroll
        for (int j = 0; j < 8; j++) acc[i][j] = 0.f;

    for (int kk = 0; kk < EMB; kk += BK) {
#pragma unroll
        for (int i = 0; i < 2; i++) {
            int v = tid + i * GTHREADS;
            int m = v >> 2;
            int k = (v & 3) << 2;
            float4 a = *(const float4*)&emb[(size_t)stok[m] * EMB + kk + k];
            As[k + 0][m] = a.x; As[k + 1][m] = a.y;
            As[k + 2][m] = a.z; As[k + 3][m] = a.w;
            float4 b = *(const float4*)&Wi2h[(size_t)(r0 + m) * WSTRIDE + kk + k];
            Bs[k + 0][m] = b.x; Bs[k + 1][m] = b.y;
            Bs[k + 2][m] = b.z; Bs[k + 3][m] = b.w;
        }
        __syncthreads();
#pragma unroll
        for (int k = 0; k < BK; k++) {
            float a[8], b[8];
            *(float4*)&a[0] = *(const float4*)&As[k][ty * 8];
            *(float4*)&a[4] = *(const float4*)&As[k][ty * 8 + 4];
            *(float4*)&b[0] = *(const float4*)&Bs[k][tx * 8];
            *(float4*)&b[4] = *(const float4*)&Bs[k][tx * 8 + 4];
#pragma unroll
            for (int i = 0; i < 8; i++)
#pragma unroll
                for (int j = 0; j < 8; j++) acc[i][j] += a[i] * b[j];
        }
        __syncthreads();
    }

    float bv[8];
#pragma unroll
    for (int j = 0; j < 8; j++) bv[j] = bias[r0 + tx * 8 + j];

#pragma unroll
    for (int i = 0; i < 8; i++) {
        int t = t0 + ty * 8 + i;
        float o[8];
#pragma unroll
        for (int j = 0; j < 8; j++) o[j] = acc[i][j] + bv[j];
        *(float4*)&g_X[(size_t)t * HID + r0 + tx * 8]     = *(float4*)&o[0];
        *(float4*)&g_X[(size_t)t * HID + r0 + tx * 8 + 4] = *(float4*)&o[4];
    }
}

// ---------------- generic square product: C = A @ A ------------------------
template <int ASTRIDE, int AOFF>
__global__ void __launch_bounds__(GTHREADS, 1)
gemm_sq_kernel(const float* __restrict__ A, float* __restrict__ C) {
    __shared__ __align__(16) float As[BK][BM + 4];
    __shared__ __align__(16) float Bs[BK][BN + 4];

    const int tid = threadIdx.x;
    const int i0 = blockIdx.y * BM;
    const int j0 = blockIdx.x * BN;

    const int tx = tid & 15;
    const int ty = tid >> 4;

    float acc[8][8];
#pragma unroll
    for (int i = 0; i < 8; i++)
#pragma unroll
        for (int j = 0; j < 8; j++) acc[i][j] = 0.f;

    for (int kk = 0; kk < HID; kk += BK) {
#pragma unroll
        for (int i = 0; i < 2; i++) {
            int v = tid + i * GTHREADS;
            int m = v >> 2;
            int k = (v & 3) << 2;
            float4 a = *(const float4*)&A[(size_t)(i0 + m) * ASTRIDE + AOFF + kk + k];
            As[k + 0][m] = a.x; As[k + 1][m] = a.y;
            As[k + 2][m] = a.z; As[k + 3][m] = a.w;
        }
#pragma unroll
        for (int i = 0; i < 2; i++) {
            int v = tid + i * GTHREADS;
            int k = v >> 5;
            int j = (v & 31) << 2;
            float4 b = *(const float4*)&A[(size_t)(kk + k) * ASTRIDE + AOFF + j0 + j];
            *(float4*)&Bs[k][j] = b;
        }
        __syncthreads();
#pragma unroll
        for (int k = 0; k < BK; k++) {
            float a[8], b[8];
            *(float4*)&a[0] = *(const float4*)&As[k][ty * 8];
            *(float4*)&a[4] = *(const float4*)&As[k][ty * 8 + 4];
            *(float4*)&b[0] = *(const float4*)&Bs[k][tx * 8];
            *(float4*)&b[4] = *(const float4*)&Bs[k][tx * 8 + 4];
#pragma unroll
            for (int i = 0; i < 8; i++)
#pragma unroll
                for (int j = 0; j < 8; j++) acc[i][j] += a[i] * b[j];
        }
        __syncthreads();
    }

#pragma unroll
    for (int i = 0; i < 8; i++) {
        int r = i0 + ty * 8 + i;
        *(float4*)&C[(size_t)r * HID + j0 + tx * 8]     = *(float4*)&acc[i][0];
        *(float4*)&C[(size_t)r * HID + j0 + tx * 8 + 4] = *(float4*)&acc[i][4];
    }
}

// ---------------- fold: Y[s] = W @ Xin[2s] + Xin[2s+1] ---------------------
template <int WSTRIDE_, int WOFF>
__global__ void __launch_bounds__(GTHREADS, 1)
gemm_fold_kernel(const float* __restrict__ W,
                 const float* __restrict__ Xin,
                 float* __restrict__ Y) {
    __shared__ __align__(16) float As[BK][BM + 4];
    __shared__ __align__(16) float Bs[BK][BN + 4];

    const int tid = threadIdx.x;
    const int s0 = blockIdx.y * BM;
    const int r0 = blockIdx.x * BN;

    const int tx = tid & 15;
    const int ty = tid >> 4;

    float acc[8][8];
#pragma unroll
    for (int i = 0; i < 8; i++)
#pragma unroll
        for (int j = 0; j < 8; j++) acc[i][j] = 0.f;

    for (int kk = 0; kk < HID; kk += BK) {
#pragma unroll
        for (int i = 0; i < 2; i++) {
            int v = tid + i * GTHREADS;
            int m = v >> 2;
            int k = (v & 3) << 2;
            float4 a = *(const float4*)&Xin[(size_t)(2 * (s0 + m)) * HID + kk + k];
            As[k + 0][m] = a.x; As[k + 1][m] = a.y;
            As[k + 2][m] = a.z; As[k + 3][m] = a.w;
            float4 b = *(const float4*)&W[(size_t)(r0 + m) * WSTRIDE_ + WOFF + kk + k];
            Bs[k + 0][m] = b.x; Bs[k + 1][m] = b.y;
            Bs[k + 2][m] = b.z; Bs[k + 3][m] = b.w;
        }
        __syncthreads();
#pragma unroll
        for (int k = 0; k < BK; k++) {
            float a[8], b[8];
            *(float4*)&a[0] = *(const float4*)&As[k][ty * 8];
            *(float4*)&a[4] = *(const float4*)&As[k][ty * 8 + 4];
            *(float4*)&b[0] = *(const float4*)&Bs[k][tx * 8];
            *(float4*)&b[4] = *(const float4*)&Bs[k][tx * 8 + 4];
#pragma unroll
            for (int i = 0; i < 8; i++)
#pragma unroll
                for (int j = 0; j < 8; j++) acc[i][j] += a[i] * b[j];
        }
        __syncthreads();
    }

#pragma unroll
    for (int i = 0; i < 8; i++) {
        int s = s0 + ty * 8 + i;
        float4 e0 = *(const float4*)&Xin[(size_t)(2 * s + 1) * HID + r0 + tx * 8];
        float4 e1 = *(const float4*)&Xin[(size_t)(2 * s + 1) * HID + r0 + tx * 8 + 4];
        float o[8];
        o[0] = acc[i][0] + e0.x; o[1] = acc[i][1] + e0.y;
        o[2] = acc[i][2] + e0.z; o[3] = acc[i][3] + e0.w;
        o[4] = acc[i][4] + e1.x; o[5] = acc[i][5] + e1.y;
        o[6] = acc[i][6] + e1.z; o[7] = acc[i][7] + e1.w;
        *(float4*)&Y[(size_t)s * HID + r0 + tx * 8]     = *(float4*)&o[0];
        *(float4*)&Y[(size_t)s * HID + r0 + tx * 8 + 4] = *(float4*)&o[4];
    }
}

// ---------------- persistent recurrence kernel (256 steps, W8/X8) ---------
#define ROWS_PER_CTA (HID / NCTA)  // 16
#define RTHREADS 512

__global__ void __launch_bounds__(RTHREADS, 1)
rnn_kernel(const float* __restrict__ Wh2o,
           const float* __restrict__ bh2o,
           float* __restrict__ out) {
    __shared__ __align__(16) float sh[HID];
    __shared__ float sred[64];

    const int tid = threadIdx.x;
    const int cta = blockIdx.x;
    const int r0  = cta * ROWS_PER_CTA;
    const int repl = cta & (NREP - 1);

    const int w = tid >> 5, l = tid & 31;
    const int grp = w & 3;
    const int q   = w >> 2;

    unsigned long long Wr[4][8];
#pragma unroll
    for (int rr = 0; rr < 4; rr++)
#pragma unroll
        for (int k = 0; k < 4; k++) {
            float4 wv = *(const float4*)&g_W8[
                (size_t)(r0 + 4 * grp + rr) * HID
                + (q << 9) + (l << 2) + (k << 7)];
            Wr[rr][2 * k]     = pack2(wv.x, wv.y);
            Wr[rr][2 * k + 1] = pack2(wv.z, wv.w);
        }

    for (int t = 0; t < SEQ8; t++) {
        float xv = 0.f;
        if (tid < ROWS_PER_CTA) xv = __ldcg(&g_X8[(size_t)t * HID + r0 + tid]);

        if (t > 0) {
            if (w == 0) {
                const unsigned tgt = (unsigned)t << 7;
                unsigned e;
                do { e = ld_relaxed(&g_cnt); }
                while (__any_sync(0xffffffffu, e < tgt));
                fence_acq();
            }
            __syncthreads();

            const float* hprev = g_hrep[(t - 1) & 1][repl];
            float4 ch = __ldcg((const float4*)&hprev[(w << 7) + (l << 2)]);
            *(float4*)&sh[(w << 7) + (l << 2)] = ch;
            __syncthreads();

            const float4* sh4 = (const float4*)sh;
            unsigned long long acc2[4];
#pragma unroll
            for (int rr = 0; rr < 4; rr++) acc2[rr] = 0ull;

#pragma unroll
            for (int k = 0; k < 4; k++) {
                float4 hv = sh4[(q << 7) + (k << 5) + l];
                unsigned long long h0 = pack2(hv.x, hv.y);
                unsigned long long h1 = pack2(hv.z, hv.w);
#pragma unroll
                for (int rr = 0; rr < 4; rr++) {
                    ffma2(acc2[rr], Wr[rr][2 * k],     h0);
                    ffma2(acc2[rr], Wr[rr][2 * k + 1], h1);
                }
            }

#pragma unroll
            for (int rr = 0; rr < 4; rr++) {
                float lo, hi;
                unpack2(lo, hi, acc2[rr]);
                float v = lo + hi;
                v += __shfl_xor_sync(0xffffffffu, v, 16);
                v += __shfl_xor_sync(0xffffffffu, v, 8);
                v += __shfl_xor_sync(0xffffffffu, v, 4);
                v += __shfl_xor_sync(0xffffffffu, v, 2);
                v += __shfl_xor_sync(0xffffffffu, v, 1);
                if (l == 0) sred[w * 4 + rr] = v;
            }
            __syncthreads();

            if (tid < ROWS_PER_CTA) {
                int g = tid >> 2, rr = tid & 3;
                float v = xv;
#pragma unroll
                for (int qq = 0; qq < 4; qq++)
                    v += sred[((qq << 2) | g) * 4 + rr];
#pragma unroll
                for (int r = 0; r < NREP; r++)
                    g_hrep[t & 1][r][r0 + tid] = v;
            }
        } else {
            if (tid < ROWS_PER_CTA) {
#pragma unroll
                for (int r = 0; r < NREP; r++)
                    g_hrep[0][r][r0 + tid] = xv;
            }
        }

        if (w == 0) {
            __syncwarp();
            if (l == 0) red_add_release(&g_cnt, 1u);
        }
    }

    // readout
    if (cta == 0) {
        if (w == 0) {
            const unsigned tgt = (unsigned)SEQ8 << 7;
            unsigned e;
            do { e = ld_relaxed(&g_cnt); }
            while (__any_sync(0xffffffffu, e < tgt));
            fence_acq();
        }
        __syncthreads();
        const float* hf = g_hrep[(SEQ8 - 1) & 1][0];
        float s = 0.f;
        for (int j = tid; j < HID; j += RTHREADS) s += __ldcg(&hf[j]) * Wh2o[j];
#pragma unroll
        for (int o = 16; o > 0; o >>= 1) s += __shfl_xor_sync(0xffffffffu, s, o);
        __syncthreads();
        if (l == 0) sred[w] = s;
        __syncthreads();
        if (tid == 0) {
            float tot = 0.f;
#pragma unroll
            for (int i = 0; i < RTHREADS / 32; i++) tot += sred[i];
            tot += bh2o[0];
            out[0] = 1.f / (1.f + expf(-tot));
        }
    }
}

// ---------------- launch ---------------------------------------------------
extern "C" void kernel_launch(void* const* d_in, const int* in_sizes, int n_in,
                              void* d_out, int out_size) {
    const int*   toks = (const int*)d_in[0];
    const float* emb  = (const float*)d_in[1];
    const float* Wi2h = (const float*)d_in[2];
    const float* bi2h = (const float*)d_in[3];
    const float* Wh2o = (const float*)d_in[4];
    const float* bh2o = (const float*)d_in[5];
    float* out = (float*)d_out;

    float* gX;  cudaGetSymbolAddress((void**)&gX,  g_X);
    float* gX2; cudaGetSymbolAddress((void**)&gX2, g_X2);
    float* gX4; cudaGetSymbolAddress((void**)&gX4, g_X4);
    float* gX8; cudaGetSymbolAddress((void**)&gX8, g_X8);
    float* gW2; cudaGetSymbolAddress((void**)&gW2, g_W2);
    float* gW4; cudaGetSymbolAddress((void**)&gW4, g_W4);
    float* gW8; cudaGetSymbolAddress((void**)&gW8, g_W8);

    reset_kernel<<<1, 32>>>();
    detect_tok_kernel<<<1, 256>>>(toks);
    gemm_x_kernel<<<dim3(HID / BN, SEQ / BM), GTHREADS>>>(toks, emb, Wi2h, bi2h);
    gemm_sq_kernel<WSTRIDE, EMB><<<dim3(HID / BN, HID / BM), GTHREADS>>>(Wi2h, gW2);
    gemm_fold_kernel<WSTRIDE, EMB><<<dim3(HID / BN, SEQ2 / BM), GTHREADS>>>(Wi2h, gX, gX2);
    gemm_sq_kernel<HID, 0><<<dim3(HID / BN, HID / BM), GTHREADS>>>(gW2, gW4);
    gemm_fold_kernel<HID, 0><<<dim3(HID / BN, SEQ4 / BM), GTHREADS>>>(gW2, gX2, gX4);
    gemm_sq_kernel<HID, 0><<<dim3(HID / BN, HID / BM), GTHREADS>>>(gW4, gW8);
    gemm_fold_kernel<HID, 0><<<dim3(HID / BN, SEQ8 / BM), GTHREADS>>>(gW4, gX4, gX8);
    rnn_kernel<<<NCTA, RTHREADS>>>(Wh2o, bh2o, out);
}

// round 13
// speedup vs baseline: 2.8123x; 1.1498x over previous
#include <cuda_runtime.h>
#include <math.h>

#define SEQ   2048
#define SEQ2  (SEQ / 2)
#define SEQ4  (SEQ / 4)
#define SEQ8  (SEQ / 8)       // 256 blocked-8 steps
#define EMB   1024
#define HID   2048
#define VOCAB 50257
#define WSTRIDE (EMB + HID)   // 3072, row stride of W_i2h

#define NCTA 128
#define NREP 4

// ---------------- scratch (device globals: allocation-free rule) ----------
__device__ __align__(16) float g_X [SEQ  * HID];
__device__ __align__(16) float g_X2[SEQ2 * HID];
__device__ __align__(16) float g_X4[SEQ4 * HID];
__device__ __align__(16) float g_X8[SEQ8 * HID];
__device__ __align__(16) float g_W2[HID * HID];
__device__ __align__(16) float g_W4[HID * HID];
__device__ __align__(16) float g_W8[HID * HID];
__device__ __align__(16) float g_hrep[2][NREP][HID];
__device__ unsigned g_cnt;
__device__ int g_tok64 = 0;

// ---------------- memory-order / packed-math helpers ----------------------
__device__ __forceinline__ unsigned ld_relaxed(const unsigned* p) {
    unsigned v;
    asm volatile("ld.relaxed.gpu.global.u32 %0, [%1];" : "=r"(v) : "l"(p) : "memory");
    return v;
}
__device__ __forceinline__ void red_add_release(unsigned* p, unsigned v) {
    asm volatile("red.release.gpu.global.add.u32 [%0], %1;" :: "l"(p), "r"(v) : "memory");
}
__device__ __forceinline__ void fence_acq() {
    asm volatile("fence.acq_rel.gpu;" ::: "memory");
}
__device__ __forceinline__ unsigned long long pack2(float lo, float hi) {
    unsigned long long r;
    asm("mov.b64 %0, {%1, %2};" : "=l"(r) : "f"(lo), "f"(hi));
    return r;
}
__device__ __forceinline__ void unpack2(float& lo, float& hi, unsigned long long v) {
    asm("mov.b64 {%0, %1}, %2;" : "=f"(lo), "=f"(hi) : "l"(v));
}
__device__ __forceinline__ void ffma2(unsigned long long& acc,
                                      unsigned long long a, unsigned long long b) {
    asm("fma.rn.f32x2 %0, %1, %2, %0;" : "+l"(acc) : "l"(a), "l"(b));
}

// ---------------- per-launch reset ----------------------------------------
__global__ void reset_kernel() {
    if (threadIdx.x == 0) g_cnt = 0;
}

// ---------------- token dtype detection -----------------------------------
__global__ void detect_tok_kernel(const int* __restrict__ p) {
    __shared__ int bad;
    if (threadIdx.x == 0) bad = 0;
    __syncthreads();
    int mybad = 0;
    for (int i = threadIdx.x; i < SEQ / 2; i += blockDim.x) {
        int lo = p[2 * i];
        int hi = p[2 * i + 1];
        if (hi != 0 || lo < 0 || lo >= VOCAB) mybad = 1;
    }
    if (mybad) atomicOr(&bad, 1);
    __syncthreads();
    if (threadIdx.x == 0) g_tok64 = bad ? 0 : 1;
}

// =================== GEMM tiles: 128x128x16, 256 thr, 8x8 micro ==========
// (R9/R12 plain-FFMA micro-kernel — proven 43 TF/s, regs 127, 2 CTA/SM.)
#define BM 128
#define BN 128
#define BK 16
#define GTHREADS 256

// ---------------- X = E @ W_e^T + b ---------------------------------------
__global__ void __launch_bounds__(GTHREADS, 1)
gemm_x_kernel(const int* __restrict__ toks,
              const float* __restrict__ emb,
              const float* __restrict__ Wi2h,
              const float* __restrict__ bias) {
    __shared__ __align__(16) float As[BK][BM + 4];
    __shared__ __align__(16) float Bs[BK][BN + 4];
    __shared__ int stok[BM];

    const int tid = threadIdx.x;
    const int t0 = blockIdx.y * BM;
    const int r0 = blockIdx.x * BN;
    const int tok64 = g_tok64;

    if (tid < BM) {
        int t = t0 + tid;
        stok[tid] = tok64 ? toks[2 * t] : toks[t];
    }
    __syncthreads();

    const int tx = tid & 15;
    const int ty = tid >> 4;

    float acc[8][8];
#pragma unroll
    for (int i = 0; i < 8; i++)
#pragma unroll
        for (int j = 0; j < 8; j++) acc[i][j] = 0.f;

    for (int kk = 0; kk < EMB; kk += BK) {
#pragma unroll
        for (int i = 0; i < 2; i++) {
            int v = tid + i * GTHREADS;
            int m = v >> 2;
            int k = (v & 3) << 2;
            float4 a = *(const float4*)&emb[(size_t)stok[m] * EMB + kk + k];
            As[k + 0][m] = a.x; As[k + 1][m] = a.y;
            As[k + 2][m] = a.z; As[k + 3][m] = a.w;
            float4 b = *(const float4*)&Wi2h[(size_t)(r0 + m) * WSTRIDE + kk + k];
            Bs[k + 0][m] = b.x; Bs[k + 1][m] = b.y;
            Bs[k + 2][m] = b.z; Bs[k + 3][m] = b.w;
        }
        __syncthreads();
#pragma unroll
        for (int k = 0; k < BK; k++) {
            float a[8], b[8];
            *(float4*)&a[0] = *(const float4*)&As[k][ty * 8];
            *(float4*)&a[4] = *(const float4*)&As[k][ty * 8 + 4];
            *(float4*)&b[0] = *(const float4*)&Bs[k][tx * 8];
            *(float4*)&b[4] = *(const float4*)&Bs[k][tx * 8 + 4];
#pragma unroll
            for (int i = 0; i < 8; i++)
#pragma unroll
                for (int j = 0; j < 8; j++) acc[i][j] += a[i] * b[j];
        }
        __syncthreads();
    }

    float bv[8];
#pragma unroll
    for (int j = 0; j < 8; j++) bv[j] = bias[r0 + tx * 8 + j];

#pragma unroll
    for (int i = 0; i < 8; i++) {
        int t = t0 + ty * 8 + i;
        float o[8];
#pragma unroll
        for (int j = 0; j < 8; j++) o[j] = acc[i][j] + bv[j];
        *(float4*)&g_X[(size_t)t * HID + r0 + tx * 8]     = *(float4*)&o[0];
        *(float4*)&g_X[(size_t)t * HID + r0 + tx * 8 + 4] = *(float4*)&o[4];
    }
}

// ---------------- generic square product: C = A @ A ------------------------
template <int ASTRIDE, int AOFF>
__global__ void __launch_bounds__(GTHREADS, 1)
gemm_sq_kernel(const float* __restrict__ A, float* __restrict__ C) {
    __shared__ __align__(16) float As[BK][BM + 4];
    __shared__ __align__(16) float Bs[BK][BN + 4];

    const int tid = threadIdx.x;
    const int i0 = blockIdx.y * BM;
    const int j0 = blockIdx.x * BN;

    const int tx = tid & 15;
    const int ty = tid >> 4;

    float acc[8][8];
#pragma unroll
    for (int i = 0; i < 8; i++)
#pragma unroll
        for (int j = 0; j < 8; j++) acc[i][j] = 0.f;

    for (int kk = 0; kk < HID; kk += BK) {
#pragma unroll
        for (int i = 0; i < 2; i++) {
            int v = tid + i * GTHREADS;
            int m = v >> 2;
            int k = (v & 3) << 2;
            float4 a = *(const float4*)&A[(size_t)(i0 + m) * ASTRIDE + AOFF + kk + k];
            As[k + 0][m] = a.x; As[k + 1][m] = a.y;
            As[k + 2][m] = a.z; As[k + 3][m] = a.w;
        }
#pragma unroll
        for (int i = 0; i < 2; i++) {
            int v = tid + i * GTHREADS;
            int k = v >> 5;
            int j = (v & 31) << 2;
            float4 b = *(const float4*)&A[(size_t)(kk + k) * ASTRIDE + AOFF + j0 + j];
            *(float4*)&Bs[k][j] = b;
        }
        __syncthreads();
#pragma unroll
        for (int k = 0; k < BK; k++) {
            float a[8], b[8];
            *(float4*)&a[0] = *(const float4*)&As[k][ty * 8];
            *(float4*)&a[4] = *(const float4*)&As[k][ty * 8 + 4];
            *(float4*)&b[0] = *(const float4*)&Bs[k][tx * 8];
            *(float4*)&b[4] = *(const float4*)&Bs[k][tx * 8 + 4];
#pragma unroll
            for (int i = 0; i < 8; i++)
#pragma unroll
                for (int j = 0; j < 8; j++) acc[i][j] += a[i] * b[j];
        }
        __syncthreads();
    }

#pragma unroll
    for (int i = 0; i < 8; i++) {
        int r = i0 + ty * 8 + i;
        *(float4*)&C[(size_t)r * HID + j0 + tx * 8]     = *(float4*)&acc[i][0];
        *(float4*)&C[(size_t)r * HID + j0 + tx * 8 + 4] = *(float4*)&acc[i][4];
    }
}

// ---------------- fold: Y[s] = W @ Xin[2s] + Xin[2s+1] ---------------------
template <int WSTRIDE_, int WOFF>
__global__ void __launch_bounds__(GTHREADS, 1)
gemm_fold_kernel(const float* __restrict__ W,
                 const float* __restrict__ Xin,
                 float* __restrict__ Y) {
    __shared__ __align__(16) float As[BK][BM + 4];
    __shared__ __align__(16) float Bs[BK][BN + 4];

    const int tid = threadIdx.x;
    const int s0 = blockIdx.y * BM;
    const int r0 = blockIdx.x * BN;

    const int tx = tid & 15;
    const int ty = tid >> 4;

    float acc[8][8];
#pragma unroll
    for (int i = 0; i < 8; i++)
#pragma unroll
        for (int j = 0; j < 8; j++) acc[i][j] = 0.f;

    for (int kk = 0; kk < HID; kk += BK) {
#pragma unroll
        for (int i = 0; i < 2; i++) {
            int v = tid + i * GTHREADS;
            int m = v >> 2;
            int k = (v & 3) << 2;
            float4 a = *(const float4*)&Xin[(size_t)(2 * (s0 + m)) * HID + kk + k];
            As[k + 0][m] = a.x; As[k + 1][m] = a.y;
            As[k + 2][m] = a.z; As[k + 3][m] = a.w;
            float4 b = *(const float4*)&W[(size_t)(r0 + m) * WSTRIDE_ + WOFF + kk + k];
            Bs[k + 0][m] = b.x; Bs[k + 1][m] = b.y;
            Bs[k + 2][m] = b.z; Bs[k + 3][m] = b.w;
        }
        __syncthreads();
#pragma unroll
        for (int k = 0; k < BK; k++) {
            float a[8], b[8];
            *(float4*)&a[0] = *(const float4*)&As[k][ty * 8];
            *(float4*)&a[4] = *(const float4*)&As[k][ty * 8 + 4];
            *(float4*)&b[0] = *(const float4*)&Bs[k][tx * 8];
            *(float4*)&b[4] = *(const float4*)&Bs[k][tx * 8 + 4];
#pragma unroll
            for (int i = 0; i < 8; i++)
#pragma unroll
                for (int j = 0; j < 8; j++) acc[i][j] += a[i] * b[j];
        }
        __syncthreads();
    }

#pragma unroll
    for (int i = 0; i < 8; i++) {
        int s = s0 + ty * 8 + i;
        float4 e0 = *(const float4*)&Xin[(size_t)(2 * s + 1) * HID + r0 + tx * 8];
        float4 e1 = *(const float4*)&Xin[(size_t)(2 * s + 1) * HID + r0 + tx * 8 + 4];
        float o[8];
        o[0] = acc[i][0] + e0.x; o[1] = acc[i][1] + e0.y;
        o[2] = acc[i][2] + e0.z; o[3] = acc[i][3] + e0.w;
        o[4] = acc[i][4] + e1.x; o[5] = acc[i][5] + e1.y;
        o[6] = acc[i][6] + e1.z; o[7] = acc[i][7] + e1.w;
        *(float4*)&Y[(size_t)s * HID + r0 + tx * 8]     = *(float4*)&o[0];
        *(float4*)&Y[(size_t)s * HID + r0 + tx * 8 + 4] = *(float4*)&o[4];
    }
}

// ---------------- persistent recurrence kernel (256 steps, W8/X8) ---------
#define ROWS_PER_CTA (HID / NCTA)  // 16
#define RTHREADS 512

__global__ void __launch_bounds__(RTHREADS, 1)
rnn_kernel(const float* __restrict__ Wh2o,
           const float* __restrict__ bh2o,
           float* __restrict__ out) {
    __shared__ __align__(16) float sh[HID];
    __shared__ float sred[64];

    const int tid = threadIdx.x;
    const int cta = blockIdx.x;
    const int r0  = cta * ROWS_PER_CTA;
    const int repl = cta & (NREP - 1);

    const int w = tid >> 5, l = tid & 31;
    const int grp = w & 3;
    const int q   = w >> 2;

    unsigned long long Wr[4][8];
#pragma unroll
    for (int rr = 0; rr < 4; rr++)
#pragma unroll
        for (int k = 0; k < 4; k++) {
            float4 wv = *(const float4*)&g_W8[
                (size_t)(r0 + 4 * grp + rr) * HID
                + (q << 9) + (l << 2) + (k << 7)];
            Wr[rr][2 * k]     = pack2(wv.x, wv.y);
            Wr[rr][2 * k + 1] = pack2(wv.z, wv.w);
        }

    for (int t = 0; t < SEQ8; t++) {
        float xv = 0.f;
        if (tid < ROWS_PER_CTA) xv = __ldcg(&g_X8[(size_t)t * HID + r0 + tid]);

        if (t > 0) {
            if (w == 0) {
                const unsigned tgt = (unsigned)t << 7;
                unsigned e;
                do { e = ld_relaxed(&g_cnt); }
                while (__any_sync(0xffffffffu, e < tgt));
                fence_acq();
            }
            __syncthreads();

            const float* hprev = g_hrep[(t - 1) & 1][repl];
            float4 ch = __ldcg((const float4*)&hprev[(w << 7) + (l << 2)]);
            *(float4*)&sh[(w << 7) + (l << 2)] = ch;
            __syncthreads();

            const float4* sh4 = (const float4*)sh;
            unsigned long long acc2[4];
#pragma unroll
            for (int rr = 0; rr < 4; rr++) acc2[rr] = 0ull;

#pragma unroll
            for (int k = 0; k < 4; k++) {
                float4 hv = sh4[(q << 7) + (k << 5) + l];
                unsigned long long h0 = pack2(hv.x, hv.y);
                unsigned long long h1 = pack2(hv.z, hv.w);
#pragma unroll
                for (int rr = 0; rr < 4; rr++) {
                    ffma2(acc2[rr], Wr[rr][2 * k],     h0);
                    ffma2(acc2[rr], Wr[rr][2 * k + 1], h1);
                }
            }

#pragma unroll
            for (int rr = 0; rr < 4; rr++) {
                float lo, hi;
                unpack2(lo, hi, acc2[rr]);
                float v = lo + hi;
                v += __shfl_xor_sync(0xffffffffu, v, 16);
                v += __shfl_xor_sync(0xffffffffu, v, 8);
                v += __shfl_xor_sync(0xffffffffu, v, 4);
                v += __shfl_xor_sync(0xffffffffu, v, 2);
                v += __shfl_xor_sync(0xffffffffu, v, 1);
                if (l == 0) sred[w * 4 + rr] = v;
            }
            __syncthreads();

            if (tid < ROWS_PER_CTA) {
                int g = tid >> 2, rr = tid & 3;
                float v = xv;
#pragma unroll
                for (int qq = 0; qq < 4; qq++)
                    v += sred[((qq << 2) | g) * 4 + rr];
#pragma unroll
                for (int r = 0; r < NREP; r++)
                    g_hrep[t & 1][r][r0 + tid] = v;
            }
        } else {
            if (tid < ROWS_PER_CTA) {
#pragma unroll
                for (int r = 0; r < NREP; r++)
                    g_hrep[0][r][r0 + tid] = xv;
            }
        }

        if (w == 0) {
            __syncwarp();
            if (l == 0) red_add_release(&g_cnt, 1u);
        }
    }

    // readout
    if (cta == 0) {
        if (w == 0) {
            const unsigned tgt = (unsigned)SEQ8 << 7;
            unsigned e;
            do { e = ld_relaxed(&g_cnt); }
            while (__any_sync(0xffffffffu, e < tgt));
            fence_acq();
        }
        __syncthreads();
        const float* hf = g_hrep[(SEQ8 - 1) & 1][0];
        float s = 0.f;
        for (int j = tid; j < HID; j += RTHREADS) s += __ldcg(&hf[j]) * Wh2o[j];
#pragma unroll
        for (int o = 16; o > 0; o >>= 1) s += __shfl_xor_sync(0xffffffffu, s, o);
        __syncthreads();
        if (l == 0) sred[w] = s;
        __syncthreads();
        if (tid == 0) {
            float tot = 0.f;
#pragma unroll
            for (int i = 0; i < RTHREADS / 32; i++) tot += sred[i];
            tot += bh2o[0];
            out[0] = 1.f / (1.f + expf(-tot));
        }
    }
}

// ---------------- launch: fork/join two GEMM chains ------------------------
extern "C" void kernel_launch(void* const* d_in, const int* in_sizes, int n_in,
                              void* d_out, int out_size) {
    const int*   toks = (const int*)d_in[0];
    const float* emb  = (const float*)d_in[1];
    const float* Wi2h = (const float*)d_in[2];
    const float* bi2h = (const float*)d_in[3];
    const float* Wh2o = (const float*)d_in[4];
    const float* bh2o = (const float*)d_in[5];
    float* out = (float*)d_out;

    float* gX;  cudaGetSymbolAddress((void**)&gX,  g_X);
    float* gX2; cudaGetSymbolAddress((void**)&gX2, g_X2);
    float* gX4; cudaGetSymbolAddress((void**)&gX4, g_X4);
    float* gX8; cudaGetSymbolAddress((void**)&gX8, g_X8);
    float* gW2; cudaGetSymbolAddress((void**)&gW2, g_W2);
    float* gW4; cudaGetSymbolAddress((void**)&gW4, g_W4);
    float* gW8; cudaGetSymbolAddress((void**)&gW8, g_W8);

    // Side stream + events, created fresh each call (host objects only; no
    // device allocation). Not destroyed: destroying capture-referenced host
    // objects mid-capture is UB, and kernel_launch runs only a handful of
    // times (correctness + capture), so the leak is a few host handles.
    cudaStream_t sB;
    cudaStreamCreateWithFlags(&sB, cudaStreamNonBlocking);
    cudaEvent_t eFork, eW2, eW4, eX8;
    cudaEventCreateWithFlags(&eFork, cudaEventDisableTiming);
    cudaEventCreateWithFlags(&eW2,   cudaEventDisableTiming);
    cudaEventCreateWithFlags(&eW4,   cudaEventDisableTiming);
    cudaEventCreateWithFlags(&eX8,   cudaEventDisableTiming);

    // ---- main stream (0): prologue, then W-chain -----------------------
    reset_kernel<<<1, 32>>>();
    detect_tok_kernel<<<1, 256>>>(toks);
    cudaEventRecord(eFork, 0);                 // fork after detect

    // ---- side stream: X-chain ------------------------------------------
    cudaStreamWaitEvent(sB, eFork, 0);
    gemm_x_kernel<<<dim3(HID / BN, SEQ / BM), GTHREADS, 0, sB>>>(toks, emb, Wi2h, bi2h);
    gemm_fold_kernel<WSTRIDE, EMB><<<dim3(HID / BN, SEQ2 / BM), GTHREADS, 0, sB>>>(Wi2h, gX, gX2);

    // ---- main stream: W2, publish, W4, publish, W8 ----------------------
    gemm_sq_kernel<WSTRIDE, EMB><<<dim3(HID / BN, HID / BM), GTHREADS>>>(Wi2h, gW2);
    cudaEventRecord(eW2, 0);
    gemm_sq_kernel<HID, 0><<<dim3(HID / BN, HID / BM), GTHREADS>>>(gW2, gW4);
    cudaEventRecord(eW4, 0);
    gemm_sq_kernel<HID, 0><<<dim3(HID / BN, HID / BM), GTHREADS>>>(gW4, gW8);

    // ---- side stream: X4 (needs W2), X8 (needs W4), join ----------------
    cudaStreamWaitEvent(sB, eW2, 0);
    gemm_fold_kernel<HID, 0><<<dim3(HID / BN, SEQ4 / BM), GTHREADS, 0, sB>>>(gW2, gX2, gX4);
    cudaStreamWaitEvent(sB, eW4, 0);
    gemm_fold_kernel<HID, 0><<<dim3(HID / BN, SEQ8 / BM), GTHREADS, 0, sB>>>(gW4, gX4, gX8);
    cudaEventRecord(eX8, sB);

    // ---- main stream: recurrence after W8 (order) + X8 (event) ---------
    cudaStreamWaitEvent(0, eX8, 0);
    rnn_kernel<<<NCTA, RTHREADS>>>(Wh2o, bh2o, out);
}

// round 15
// speedup vs baseline: 3.3903x; 1.2055x over previous
#include <cuda_runtime.h>
#include <cuda_bf16.h>
#include <mma.h>
#include <math.h>
#include <stdint.h>

using namespace nvcuda;

#define SEQ   2048
#define SEQ2  (SEQ / 2)
#define SEQ4  (SEQ / 4)
#define SEQ8  (SEQ / 8)       // 256 blocked-8 steps
#define EMB   1024
#define HID   2048
#define VOCAB 50257
#define WSTRIDE (EMB + HID)   // 3072, row stride of W_i2h

#define NCTA 128
#define NREP 4

// ---------------- scratch (device globals: allocation-free rule) ----------
__device__ __align__(16) float g_X [SEQ  * HID];
__device__ __align__(16) float g_X2[SEQ2 * HID];
__device__ __align__(16) float g_X4[SEQ4 * HID];
__device__ __align__(16) float g_X8[SEQ8 * HID];
__device__ __align__(16) float g_W2[HID * HID];
__device__ __align__(16) float g_W4[HID * HID];
__device__ __align__(16) float g_W8[HID * HID];
__device__ __align__(16) float g_hrep[2][NREP][HID];
__device__ unsigned g_cnt;
__device__ int g_tok64 = 0;

// ---------------- memory-order / packed-math helpers ----------------------
__device__ __forceinline__ unsigned ld_relaxed(const unsigned* p) {
    unsigned v;
    asm volatile("ld.relaxed.gpu.global.u32 %0, [%1];" : "=r"(v) : "l"(p) : "memory");
    return v;
}
__device__ __forceinline__ void red_add_release(unsigned* p, unsigned v) {
    asm volatile("red.release.gpu.global.add.u32 [%0], %1;" :: "l"(p), "r"(v) : "memory");
}
__device__ __forceinline__ void fence_acq() {
    asm volatile("fence.acq_rel.gpu;" ::: "memory");
}
__device__ __forceinline__ unsigned long long pack2(float lo, float hi) {
    unsigned long long r;
    asm("mov.b64 %0, {%1, %2};" : "=l"(r) : "f"(lo), "f"(hi));
    return r;
}
__device__ __forceinline__ void unpack2(float& lo, float& hi, unsigned long long v) {
    asm("mov.b64 {%0, %1}, %2;" : "=f"(lo), "=f"(hi) : "l"(v));
}
__device__ __forceinline__ void ffma2(unsigned long long& acc,
                                      unsigned long long a, unsigned long long b) {
    asm("fma.rn.f32x2 %0, %1, %2, %0;" : "+l"(acc) : "l"(a), "l"(b));
}

// bf16 hi/lo split of two floats, packed as bf16x2 words (lo element in low 16)
__device__ __forceinline__ void bf16_split(float x0, float x1,
                                           uint32_t& hip, uint32_t& lop) {
    uint32_t b0 = __float_as_uint(x0), b1 = __float_as_uint(x1);
    hip = (b1 & 0xFFFF0000u) | (b0 >> 16);          // truncation split
    float l0 = x0 - __uint_as_float(b0 & 0xFFFF0000u);
    float l1 = x1 - __uint_as_float(b1 & 0xFFFF0000u);
    asm("cvt.rn.satfinite.bf16x2.f32 %0, %1, %2;" : "=r"(lop) : "f"(l1), "f"(l0));
}

// ---------------- per-launch reset ----------------------------------------
__global__ void reset_kernel() {
    if (threadIdx.x == 0) g_cnt = 0;
}

// ---------------- token dtype detection -----------------------------------
__global__ void detect_tok_kernel(const int* __restrict__ p) {
    __shared__ int bad;
    if (threadIdx.x == 0) bad = 0;
    __syncthreads();
    int mybad = 0;
    for (int i = threadIdx.x; i < SEQ / 2; i += blockDim.x) {
        int lo = p[2 * i];
        int hi = p[2 * i + 1];
        if (hi != 0 || lo < 0 || lo >= VOCAB) mybad = 1;
    }
    if (mybad) atomicOr(&bad, 1);
    __syncthreads();
    if (threadIdx.x == 0) g_tok64 = bad ? 0 : 1;
}

// =================== SIMT GEMM tiles (X + folds; proven) ==================
#define BM 128
#define BN 128
#define BK 16
#define GTHREADS 256

// ---------------- X = E @ W_e^T + b ---------------------------------------
__global__ void __launch_bounds__(GTHREADS, 1)
gemm_x_kernel(const int* __restrict__ toks,
              const float* __restrict__ emb,
              const float* __restrict__ Wi2h,
              const float* __restrict__ bias) {
    __shared__ __align__(16) float As[BK][BM + 4];
    __shared__ __align__(16) float Bs[BK][BN + 4];
    __shared__ int stok[BM];

    const int tid = threadIdx.x;
    const int t0 = blockIdx.y * BM;
    const int r0 = blockIdx.x * BN;
    const int tok64 = g_tok64;

    if (tid < BM) {
        int t = t0 + tid;
        stok[tid] = tok64 ? toks[2 * t] : toks[t];
    }
    __syncthreads();

    const int tx = tid & 15;
    const int ty = tid >> 4;

    float acc[8][8];
#pragma unroll
    for (int i = 0; i < 8; i++)
#pragma unroll
        for (int j = 0; j < 8; j++) acc[i][j] = 0.f;

    for (int kk = 0; kk < EMB; kk += BK) {
#pragma unroll
        for (int i = 0; i < 2; i++) {
            int v = tid + i * GTHREADS;
            int m = v >> 2;
            int k = (v & 3) << 2;
            float4 a = *(const float4*)&emb[(size_t)stok[m] * EMB + kk + k];
            As[k + 0][m] = a.x; As[k + 1][m] = a.y;
            As[k + 2][m] = a.z; As[k + 3][m] = a.w;
            float4 b = *(const float4*)&Wi2h[(size_t)(r0 + m) * WSTRIDE + kk + k];
            Bs[k + 0][m] = b.x; Bs[k + 1][m] = b.y;
            Bs[k + 2][m] = b.z; Bs[k + 3][m] = b.w;
        }
        __syncthreads();
#pragma unroll
        for (int k = 0; k < BK; k++) {
            float a[8], b[8];
            *(float4*)&a[0] = *(const float4*)&As[k][ty * 8];
            *(float4*)&a[4] = *(const float4*)&As[k][ty * 8 + 4];
            *(float4*)&b[0] = *(const float4*)&Bs[k][tx * 8];
            *(float4*)&b[4] = *(const float4*)&Bs[k][tx * 8 + 4];
#pragma unroll
            for (int i = 0; i < 8; i++)
#pragma unroll
                for (int j = 0; j < 8; j++) acc[i][j] += a[i] * b[j];
        }
        __syncthreads();
    }

    float bv[8];
#pragma unroll
    for (int j = 0; j < 8; j++) bv[j] = bias[r0 + tx * 8 + j];

#pragma unroll
    for (int i = 0; i < 8; i++) {
        int t = t0 + ty * 8 + i;
        float o[8];
#pragma unroll
        for (int j = 0; j < 8; j++) o[j] = acc[i][j] + bv[j];
        *(float4*)&g_X[(size_t)t * HID + r0 + tx * 8]     = *(float4*)&o[0];
        *(float4*)&g_X[(size_t)t * HID + r0 + tx * 8 + 4] = *(float4*)&o[4];
    }
}

// ---------------- fold: Y[s] = W @ Xin[2s] + Xin[2s+1] ---------------------
template <int WSTRIDE_, int WOFF>
__global__ void __launch_bounds__(GTHREADS, 1)
gemm_fold_kernel(const float* __restrict__ W,
                 const float* __restrict__ Xin,
                 float* __restrict__ Y) {
    __shared__ __align__(16) float As[BK][BM + 4];
    __shared__ __align__(16) float Bs[BK][BN + 4];

    const int tid = threadIdx.x;
    const int s0 = blockIdx.y * BM;
    const int r0 = blockIdx.x * BN;

    const int tx = tid & 15;
    const int ty = tid >> 4;

    float acc[8][8];
#pragma unroll
    for (int i = 0; i < 8; i++)
#pragma unroll
        for (int j = 0; j < 8; j++) acc[i][j] = 0.f;

    for (int kk = 0; kk < HID; kk += BK) {
#pragma unroll
        for (int i = 0; i < 2; i++) {
            int v = tid + i * GTHREADS;
            int m = v >> 2;
            int k = (v & 3) << 2;
            float4 a = *(const float4*)&Xin[(size_t)(2 * (s0 + m)) * HID + kk + k];
            As[k + 0][m] = a.x; As[k + 1][m] = a.y;
            As[k + 2][m] = a.z; As[k + 3][m] = a.w;
            float4 b = *(const float4*)&W[(size_t)(r0 + m) * WSTRIDE_ + WOFF + kk + k];
            Bs[k + 0][m] = b.x; Bs[k + 1][m] = b.y;
            Bs[k + 2][m] = b.z; Bs[k + 3][m] = b.w;
        }
        __syncthreads();
#pragma unroll
        for (int k = 0; k < BK; k++) {
            float a[8], b[8];
            *(float4*)&a[0] = *(const float4*)&As[k][ty * 8];
            *(float4*)&a[4] = *(const float4*)&As[k][ty * 8 + 4];
            *(float4*)&b[0] = *(const float4*)&Bs[k][tx * 8];
            *(float4*)&b[4] = *(const float4*)&Bs[k][tx * 8 + 4];
#pragma unroll
            for (int i = 0; i < 8; i++)
#pragma unroll
                for (int j = 0; j < 8; j++) acc[i][j] += a[i] * b[j];
        }
        __syncthreads();
    }

#pragma unroll
    for (int i = 0; i < 8; i++) {
        int s = s0 + ty * 8 + i;
        float4 e0 = *(const float4*)&Xin[(size_t)(2 * s + 1) * HID + r0 + tx * 8];
        float4 e1 = *(const float4*)&Xin[(size_t)(2 * s + 1) * HID + r0 + tx * 8 + 4];
        float o[8];
        o[0] = acc[i][0] + e0.x; o[1] = acc[i][1] + e0.y;
        o[2] = acc[i][2] + e0.z; o[3] = acc[i][3] + e0.w;
        o[4] = acc[i][4] + e1.x; o[5] = acc[i][5] + e1.y;
        o[6] = acc[i][6] + e1.z; o[7] = acc[i][7] + e1.w;
        *(float4*)&Y[(size_t)s * HID + r0 + tx * 8]     = *(float4*)&o[0];
        *(float4*)&Y[(size_t)s * HID + r0 + tx * 8 + 4] = *(float4*)&o[4];
    }
}

// =================== WMMA bf16x3 square product (tensor cores) ============
// C = A @ A (HID x HID views), fp32-accurate via bf16 hi/lo split (3 HMMAs).
// Tile: 128x128 per CTA, K-blocks of 32. 8 warps = 4(M) x 2(N), warp = 32x64.
#define WM_LDA 40               // bf16 elems per A-tile row (20 u32)
#define WM_LDB 136              // bf16 elems per B-tile row (68 u32)
#define WM_THREADS 256

template <int ASTRIDE, int AOFF>
__global__ void __launch_bounds__(WM_THREADS, 1)
gemm_sq_wmma(const float* __restrict__ A, float* __restrict__ C) {
    __shared__ uint32_t Ahi[128 * (WM_LDA / 2)], Alo[128 * (WM_LDA / 2)];
    __shared__ uint32_t Bhi[32 * (WM_LDB / 2)],  Blo[32 * (WM_LDB / 2)];

    const int tid = threadIdx.x;
    const int wid = tid >> 5;
    const int i0 = blockIdx.y * 128;
    const int j0 = blockIdx.x * 128;
    const int mw = wid >> 1;        // 0..3 -> M offset mw*32
    const int nw = wid & 1;         // 0..1 -> N offset nw*64

    wmma::fragment<wmma::accumulator, 16, 16, 16, float> c[2][4];
#pragma unroll
    for (int mi = 0; mi < 2; mi++)
#pragma unroll
        for (int ni = 0; ni < 4; ni++) wmma::fill_fragment(c[mi][ni], 0.f);

    const __nv_bfloat16* pAh = (const __nv_bfloat16*)Ahi;
    const __nv_bfloat16* pAl = (const __nv_bfloat16*)Alo;
    const __nv_bfloat16* pBh = (const __nv_bfloat16*)Bhi;
    const __nv_bfloat16* pBl = (const __nv_bfloat16*)Blo;

    for (int kb = 0; kb < HID / 32; kb++) {
        const int kk = kb * 32;

        // A tile [128 rows][32 k], k contiguous, hi/lo split
#pragma unroll
        for (int i = 0; i < 8; i++) {
            int p = tid + i * WM_THREADS;      // 0..2047
            int row = p >> 4;                  // 0..127
            int kp = p & 15;                   // float2 index: k = 2*kp
            float2 a = *(const float2*)&A[(size_t)(i0 + row) * ASTRIDE + AOFF + kk + 2 * kp];
            uint32_t hip, lop;
            bf16_split(a.x, a.y, hip, lop);
            Ahi[row * (WM_LDA / 2) + kp] = hip;
            Alo[row * (WM_LDA / 2) + kp] = lop;
        }
        // B tile [32 k][128 n], n contiguous, hi/lo split
#pragma unroll
        for (int i = 0; i < 8; i++) {
            int p = tid + i * WM_THREADS;
            int kr = p >> 6;                   // 0..31
            int np = p & 63;                   // float2 index: n = 2*np
            float2 b = *(const float2*)&A[(size_t)(kk + kr) * ASTRIDE + AOFF + j0 + 2 * np];
            uint32_t hip, lop;
            bf16_split(b.x, b.y, hip, lop);
            Bhi[kr * (WM_LDB / 2) + np] = hip;
            Blo[kr * (WM_LDB / 2) + np] = lop;
        }
        __syncthreads();

#pragma unroll
        for (int ks = 0; ks < 2; ks++) {
            const int ko = ks * 16;
            wmma::fragment<wmma::matrix_a, 16, 16, 16, __nv_bfloat16, wmma::row_major> ah[2], al[2];
#pragma unroll
            for (int mi = 0; mi < 2; mi++) {
                int r = mw * 32 + mi * 16;
                wmma::load_matrix_sync(ah[mi], pAh + r * WM_LDA + ko, WM_LDA);
                wmma::load_matrix_sync(al[mi], pAl + r * WM_LDA + ko, WM_LDA);
            }
#pragma unroll
            for (int ni = 0; ni < 4; ni++) {
                int cn = nw * 64 + ni * 16;
                wmma::fragment<wmma::matrix_b, 16, 16, 16, __nv_bfloat16, wmma::row_major> bh, bl;
                wmma::load_matrix_sync(bh, pBh + ko * WM_LDB + cn, WM_LDB);
                wmma::load_matrix_sync(bl, pBl + ko * WM_LDB + cn, WM_LDB);
#pragma unroll
                for (int mi = 0; mi < 2; mi++) {
                    wmma::mma_sync(c[mi][ni], ah[mi], bh, c[mi][ni]);
                    wmma::mma_sync(c[mi][ni], ah[mi], bl, c[mi][ni]);
                    wmma::mma_sync(c[mi][ni], al[mi], bh, c[mi][ni]);
                }
            }
        }
        __syncthreads();
    }

#pragma unroll
    for (int mi = 0; mi < 2; mi++)
#pragma unroll
        for (int ni = 0; ni < 4; ni++) {
            int r = i0 + mw * 32 + mi * 16;
            int cn = j0 + nw * 64 + ni * 16;
            wmma::store_matrix_sync(&C[(size_t)r * HID + cn], c[mi][ni],
                                    HID, wmma::mem_row_major);
        }
}

// ---------------- persistent recurrence kernel (256 steps, W8/X8) ---------
#define ROWS_PER_CTA (HID / NCTA)  // 16
#define RTHREADS 512

__global__ void __launch_bounds__(RTHREADS, 1)
rnn_kernel(const float* __restrict__ Wh2o,
           const float* __restrict__ bh2o,
           float* __restrict__ out) {
    __shared__ __align__(16) float sh[HID];
    __shared__ float sred[64];

    const int tid = threadIdx.x;
    const int cta = blockIdx.x;
    const int r0  = cta * ROWS_PER_CTA;
    const int repl = cta & (NREP - 1);

    const int w = tid >> 5, l = tid & 31;
    const int grp = w & 3;
    const int q   = w >> 2;

    unsigned long long Wr[4][8];
#pragma unroll
    for (int rr = 0; rr < 4; rr++)
#pragma unroll
        for (int k = 0; k < 4; k++) {
            float4 wv = *(const float4*)&g_W8[
                (size_t)(r0 + 4 * grp + rr) * HID
                + (q << 9) + (l << 2) + (k << 7)];
            Wr[rr][2 * k]     = pack2(wv.x, wv.y);
            Wr[rr][2 * k + 1] = pack2(wv.z, wv.w);
        }

    for (int t = 0; t < SEQ8; t++) {
        float xv = 0.f;
        if (tid < ROWS_PER_CTA) xv = __ldcg(&g_X8[(size_t)t * HID + r0 + tid]);

        if (t > 0) {
            if (w == 0) {
                const unsigned tgt = (unsigned)t << 7;
                unsigned e;
                do { e = ld_relaxed(&g_cnt); }
                while (__any_sync(0xffffffffu, e < tgt));
                fence_acq();
            }
            __syncthreads();

            const float* hprev = g_hrep[(t - 1) & 1][repl];
            float4 ch = __ldcg((const float4*)&hprev[(w << 7) + (l << 2)]);
            *(float4*)&sh[(w << 7) + (l << 2)] = ch;
            __syncthreads();

            const float4* sh4 = (const float4*)sh;
            unsigned long long acc2[4];
#pragma unroll
            for (int rr = 0; rr < 4; rr++) acc2[rr] = 0ull;

#pragma unroll
            for (int k = 0; k < 4; k++) {
                float4 hv = sh4[(q << 7) + (k << 5) + l];
                unsigned long long h0 = pack2(hv.x, hv.y);
                unsigned long long h1 = pack2(hv.z, hv.w);
#pragma unroll
                for (int rr = 0; rr < 4; rr++) {
                    ffma2(acc2[rr], Wr[rr][2 * k],     h0);
                    ffma2(acc2[rr], Wr[rr][2 * k + 1], h1);
                }
            }

#pragma unroll
            for (int rr = 0; rr < 4; rr++) {
                float lo, hi;
                unpack2(lo, hi, acc2[rr]);
                float v = lo + hi;
                v += __shfl_xor_sync(0xffffffffu, v, 16);
                v += __shfl_xor_sync(0xffffffffu, v, 8);
                v += __shfl_xor_sync(0xffffffffu, v, 4);
                v += __shfl_xor_sync(0xffffffffu, v, 2);
                v += __shfl_xor_sync(0xffffffffu, v, 1);
                if (l == 0) sred[w * 4 + rr] = v;
            }
            __syncthreads();

            if (tid < ROWS_PER_CTA) {
                int g = tid >> 2, rr = tid & 3;
                float v = xv;
#pragma unroll
                for (int qq = 0; qq < 4; qq++)
                    v += sred[((qq << 2) | g) * 4 + rr];
#pragma unroll
                for (int r = 0; r < NREP; r++)
                    g_hrep[t & 1][r][r0 + tid] = v;
            }
        } else {
            if (tid < ROWS_PER_CTA) {
#pragma unroll
                for (int r = 0; r < NREP; r++)
                    g_hrep[0][r][r0 + tid] = xv;
            }
        }

        if (w == 0) {
            __syncwarp();
            if (l == 0) red_add_release(&g_cnt, 1u);
        }
    }

    // readout
    if (cta == 0) {
        if (w == 0) {
            const unsigned tgt = (unsigned)SEQ8 << 7;
            unsigned e;
            do { e = ld_relaxed(&g_cnt); }
            while (__any_sync(0xffffffffu, e < tgt));
            fence_acq();
        }
        __syncthreads();
        const float* hf = g_hrep[(SEQ8 - 1) & 1][0];
        float s = 0.f;
        for (int j = tid; j < HID; j += RTHREADS) s += __ldcg(&hf[j]) * Wh2o[j];
#pragma unroll
        for (int o = 16; o > 0; o >>= 1) s += __shfl_xor_sync(0xffffffffu, s, o);
        __syncthreads();
        if (l == 0) sred[w] = s;
        __syncthreads();
        if (tid == 0) {
            float tot = 0.f;
#pragma unroll
            for (int i = 0; i < RTHREADS / 32; i++) tot += sred[i];
            tot += bh2o[0];
            out[0] = 1.f / (1.f + expf(-tot));
        }
    }
}

// ---------------- launch: fork/join two GEMM chains ------------------------
extern "C" void kernel_launch(void* const* d_in, const int* in_sizes, int n_in,
                              void* d_out, int out_size) {
    const int*   toks = (const int*)d_in[0];
    const float* emb  = (const float*)d_in[1];
    const float* Wi2h = (const float*)d_in[2];
    const float* bi2h = (const float*)d_in[3];
    const float* Wh2o = (const float*)d_in[4];
    const float* bh2o = (const float*)d_in[5];
    float* out = (float*)d_out;

    float* gX;  cudaGetSymbolAddress((void**)&gX,  g_X);
    float* gX2; cudaGetSymbolAddress((void**)&gX2, g_X2);
    float* gX4; cudaGetSymbolAddress((void**)&gX4, g_X4);
    float* gX8; cudaGetSymbolAddress((void**)&gX8, g_X8);
    float* gW2; cudaGetSymbolAddress((void**)&gW2, g_W2);
    float* gW4; cudaGetSymbolAddress((void**)&gW4, g_W4);
    float* gW8; cudaGetSymbolAddress((void**)&gW8, g_W8);

    // Side stream + events (host objects only; see R13 note on lifetime).
    cudaStream_t sB;
    cudaStreamCreateWithFlags(&sB, cudaStreamNonBlocking);
    cudaEvent_t eFork, eW2, eW4, eX8;
    cudaEventCreateWithFlags(&eFork, cudaEventDisableTiming);
    cudaEventCreateWithFlags(&eW2,   cudaEventDisableTiming);
    cudaEventCreateWithFlags(&eW4,   cudaEventDisableTiming);
    cudaEventCreateWithFlags(&eX8,   cudaEventDisableTiming);

    const dim3 wmGrid(HID / 128, HID / 128);   // 16 x 16

    // ---- main stream (0): prologue, then W-chain (WMMA tensor cores) ----
    reset_kernel<<<1, 32>>>();
    detect_tok_kernel<<<1, 256>>>(toks);
    cudaEventRecord(eFork, 0);

    // ---- side stream: X-chain ------------------------------------------
    cudaStreamWaitEvent(sB, eFork, 0);
    gemm_x_kernel<<<dim3(HID / BN, SEQ / BM), GTHREADS, 0, sB>>>(toks, emb, Wi2h, bi2h);
    gemm_fold_kernel<WSTRIDE, EMB><<<dim3(HID / BN, SEQ2 / BM), GTHREADS, 0, sB>>>(Wi2h, gX, gX2);

    // ---- main stream: W2, W4, W8 on WMMA --------------------------------
    gemm_sq_wmma<WSTRIDE, EMB><<<wmGrid, WM_THREADS>>>(Wi2h, gW2);
    cudaEventRecord(eW2, 0);
    gemm_sq_wmma<HID, 0><<<wmGrid, WM_THREADS>>>(gW2, gW4);
    cudaEventRecord(eW4, 0);
    gemm_sq_wmma<HID, 0><<<wmGrid, WM_THREADS>>>(gW4, gW8);

    // ---- side stream: X4 (needs W2), X8 (needs W4), join ----------------
    cudaStreamWaitEvent(sB, eW2, 0);
    gemm_fold_kernel<HID, 0><<<dim3(HID / BN, SEQ4 / BM), GTHREADS, 0, sB>>>(gW2, gX2, gX4);
    cudaStreamWaitEvent(sB, eW4, 0);
    gemm_fold_kernel<HID, 0><<<dim3(HID / BN, SEQ8 / BM), GTHREADS, 0, sB>>>(gW4, gX4, gX8);
    cudaEventRecord(eX8, sB);

    // ---- main stream: recurrence after W8 (order) + X8 (event) ---------
    cudaStreamWaitEvent(0, eX8, 0);
    rnn_kernel<<<NCTA, RTHREADS>>>(Wh2o, bh2o, out);
}

// round 16
// speedup vs baseline: 3.9983x; 1.1793x over previous
#include <cuda_runtime.h>
#include <cuda_bf16.h>
#include <mma.h>
#include <math.h>
#include <stdint.h>

using namespace nvcuda;

#define SEQ   2048
#define SEQ2  (SEQ / 2)
#define SEQ4  (SEQ / 4)
#define SEQ8  (SEQ / 8)       // 256 blocked-8 steps
#define EMB   1024
#define HID   2048
#define VOCAB 50257
#define WSTRIDE (EMB + HID)   // 3072, row stride of W_i2h

#define NCTA 128
#define NREP 4

// ---------------- scratch (device globals: allocation-free rule) ----------
__device__ __align__(16) float g_X [SEQ  * HID];
__device__ __align__(16) float g_X2[SEQ2 * HID];
__device__ __align__(16) float g_X4[SEQ4 * HID];
__device__ __align__(16) float g_X8[SEQ8 * HID];
__device__ __align__(16) float g_W2[HID * HID];
__device__ __align__(16) float g_W4[HID * HID];
__device__ __align__(16) float g_W8[HID * HID];
__device__ __align__(16) float g_hrep[2][NREP][HID];
__device__ unsigned g_cnt;
__device__ int g_tok64 = 0;

// ---------------- memory-order / packed-math helpers ----------------------
__device__ __forceinline__ unsigned ld_relaxed(const unsigned* p) {
    unsigned v;
    asm volatile("ld.relaxed.gpu.global.u32 %0, [%1];" : "=r"(v) : "l"(p) : "memory");
    return v;
}
__device__ __forceinline__ void red_add_release(unsigned* p, unsigned v) {
    asm volatile("red.release.gpu.global.add.u32 [%0], %1;" :: "l"(p), "r"(v) : "memory");
}
__device__ __forceinline__ void fence_acq() {
    asm volatile("fence.acq_rel.gpu;" ::: "memory");
}
__device__ __forceinline__ unsigned long long pack2(float lo, float hi) {
    unsigned long long r;
    asm("mov.b64 %0, {%1, %2};" : "=l"(r) : "f"(lo), "f"(hi));
    return r;
}
__device__ __forceinline__ void unpack2(float& lo, float& hi, unsigned long long v) {
    asm("mov.b64 {%0, %1}, %2;" : "=f"(lo), "=f"(hi) : "l"(v));
}
__device__ __forceinline__ void ffma2(unsigned long long& acc,
                                      unsigned long long a, unsigned long long b) {
    asm("fma.rn.f32x2 %0, %1, %2, %0;" : "+l"(acc) : "l"(a), "l"(b));
}

// bf16 hi/lo split of two floats, packed as bf16x2 words (lo element in low 16)
__device__ __forceinline__ void bf16_split(float x0, float x1,
                                           uint32_t& hip, uint32_t& lop) {
    uint32_t b0 = __float_as_uint(x0), b1 = __float_as_uint(x1);
    hip = (b1 & 0xFFFF0000u) | (b0 >> 16);          // truncation split
    float l0 = x0 - __uint_as_float(b0 & 0xFFFF0000u);
    float l1 = x1 - __uint_as_float(b1 & 0xFFFF0000u);
    asm("cvt.rn.satfinite.bf16x2.f32 %0, %1, %2;" : "=r"(lop) : "f"(l1), "f"(l0));
}

// ---------------- per-launch reset ----------------------------------------
__global__ void reset_kernel() {
    if (threadIdx.x == 0) g_cnt = 0;
}

// ---------------- token dtype detection -----------------------------------
__global__ void detect_tok_kernel(const int* __restrict__ p) {
    __shared__ int bad;
    if (threadIdx.x == 0) bad = 0;
    __syncthreads();
    int mybad = 0;
    for (int i = threadIdx.x; i < SEQ / 2; i += blockDim.x) {
        int lo = p[2 * i];
        int hi = p[2 * i + 1];
        if (hi != 0 || lo < 0 || lo >= VOCAB) mybad = 1;
    }
    if (mybad) atomicOr(&bad, 1);
    __syncthreads();
    if (threadIdx.x == 0) g_tok64 = bad ? 0 : 1;
}

// =================== SIMT GEMM (X only; proven) ===========================
#define BM 128
#define BN 128
#define BK 16
#define GTHREADS 256

// ---------------- X = E @ W_e^T + b ---------------------------------------
__global__ void __launch_bounds__(GTHREADS, 1)
gemm_x_kernel(const int* __restrict__ toks,
              const float* __restrict__ emb,
              const float* __restrict__ Wi2h,
              const float* __restrict__ bias) {
    __shared__ __align__(16) float As[BK][BM + 4];
    __shared__ __align__(16) float Bs[BK][BN + 4];
    __shared__ int stok[BM];

    const int tid = threadIdx.x;
    const int t0 = blockIdx.y * BM;
    const int r0 = blockIdx.x * BN;
    const int tok64 = g_tok64;

    if (tid < BM) {
        int t = t0 + tid;
        stok[tid] = tok64 ? toks[2 * t] : toks[t];
    }
    __syncthreads();

    const int tx = tid & 15;
    const int ty = tid >> 4;

    float acc[8][8];
#pragma unroll
    for (int i = 0; i < 8; i++)
#pragma unroll
        for (int j = 0; j < 8; j++) acc[i][j] = 0.f;

    for (int kk = 0; kk < EMB; kk += BK) {
#pragma unroll
        for (int i = 0; i < 2; i++) {
            int v = tid + i * GTHREADS;
            int m = v >> 2;
            int k = (v & 3) << 2;
            float4 a = *(const float4*)&emb[(size_t)stok[m] * EMB + kk + k];
            As[k + 0][m] = a.x; As[k + 1][m] = a.y;
            As[k + 2][m] = a.z; As[k + 3][m] = a.w;
            float4 b = *(const float4*)&Wi2h[(size_t)(r0 + m) * WSTRIDE + kk + k];
            Bs[k + 0][m] = b.x; Bs[k + 1][m] = b.y;
            Bs[k + 2][m] = b.z; Bs[k + 3][m] = b.w;
        }
        __syncthreads();
#pragma unroll
        for (int k = 0; k < BK; k++) {
            float a[8], b[8];
            *(float4*)&a[0] = *(const float4*)&As[k][ty * 8];
            *(float4*)&a[4] = *(const float4*)&As[k][ty * 8 + 4];
            *(float4*)&b[0] = *(const float4*)&Bs[k][tx * 8];
            *(float4*)&b[4] = *(const float4*)&Bs[k][tx * 8 + 4];
#pragma unroll
            for (int i = 0; i < 8; i++)
#pragma unroll
                for (int j = 0; j < 8; j++) acc[i][j] += a[i] * b[j];
        }
        __syncthreads();
    }

    float bv[8];
#pragma unroll
    for (int j = 0; j < 8; j++) bv[j] = bias[r0 + tx * 8 + j];

#pragma unroll
    for (int i = 0; i < 8; i++) {
        int t = t0 + ty * 8 + i;
        float o[8];
#pragma unroll
        for (int j = 0; j < 8; j++) o[j] = acc[i][j] + bv[j];
        *(float4*)&g_X[(size_t)t * HID + r0 + tx * 8]     = *(float4*)&o[0];
        *(float4*)&g_X[(size_t)t * HID + r0 + tx * 8 + 4] = *(float4*)&o[4];
    }
}

// =================== WMMA bf16x3 kernels (tensor cores) ====================
#define WM_LDA 40               // bf16 elems per tile row (20 u32)
#define WM_THREADS 256

// ---------------- square product: C = A @ A (HID x HID views) -------------
#define WM_LDB 136              // B (k-major rows) stride for sq kernel
template <int ASTRIDE, int AOFF>
__global__ void __launch_bounds__(WM_THREADS, 1)
gemm_sq_wmma(const float* __restrict__ A, float* __restrict__ C) {
    __shared__ uint32_t Ahi[128 * (WM_LDA / 2)], Alo[128 * (WM_LDA / 2)];
    __shared__ uint32_t Bhi[32 * (WM_LDB / 2)],  Blo[32 * (WM_LDB / 2)];

    const int tid = threadIdx.x;
    const int wid = tid >> 5;
    const int i0 = blockIdx.y * 128;
    const int j0 = blockIdx.x * 128;
    const int mw = wid >> 1;        // 0..3 -> M offset mw*32
    const int nw = wid & 1;         // 0..1 -> N offset nw*64

    wmma::fragment<wmma::accumulator, 16, 16, 16, float> c[2][4];
#pragma unroll
    for (int mi = 0; mi < 2; mi++)
#pragma unroll
        for (int ni = 0; ni < 4; ni++) wmma::fill_fragment(c[mi][ni], 0.f);

    const __nv_bfloat16* pAh = (const __nv_bfloat16*)Ahi;
    const __nv_bfloat16* pAl = (const __nv_bfloat16*)Alo;
    const __nv_bfloat16* pBh = (const __nv_bfloat16*)Bhi;
    const __nv_bfloat16* pBl = (const __nv_bfloat16*)Blo;

    for (int kb = 0; kb < HID / 32; kb++) {
        const int kk = kb * 32;

#pragma unroll
        for (int i = 0; i < 8; i++) {
            int p = tid + i * WM_THREADS;
            int row = p >> 4;
            int kp = p & 15;
            float2 a = *(const float2*)&A[(size_t)(i0 + row) * ASTRIDE + AOFF + kk + 2 * kp];
            uint32_t hip, lop;
            bf16_split(a.x, a.y, hip, lop);
            Ahi[row * (WM_LDA / 2) + kp] = hip;
            Alo[row * (WM_LDA / 2) + kp] = lop;
        }
#pragma unroll
        for (int i = 0; i < 8; i++) {
            int p = tid + i * WM_THREADS;
            int kr = p >> 6;
            int np = p & 63;
            float2 b = *(const float2*)&A[(size_t)(kk + kr) * ASTRIDE + AOFF + j0 + 2 * np];
            uint32_t hip, lop;
            bf16_split(b.x, b.y, hip, lop);
            Bhi[kr * (WM_LDB / 2) + np] = hip;
            Blo[kr * (WM_LDB / 2) + np] = lop;
        }
        __syncthreads();

#pragma unroll
        for (int ks = 0; ks < 2; ks++) {
            const int ko = ks * 16;
            wmma::fragment<wmma::matrix_a, 16, 16, 16, __nv_bfloat16, wmma::row_major> ah[2], al[2];
#pragma unroll
            for (int mi = 0; mi < 2; mi++) {
                int r = mw * 32 + mi * 16;
                wmma::load_matrix_sync(ah[mi], pAh + r * WM_LDA + ko, WM_LDA);
                wmma::load_matrix_sync(al[mi], pAl + r * WM_LDA + ko, WM_LDA);
            }
#pragma unroll
            for (int ni = 0; ni < 4; ni++) {
                int cn = nw * 64 + ni * 16;
                wmma::fragment<wmma::matrix_b, 16, 16, 16, __nv_bfloat16, wmma::row_major> bh, bl;
                wmma::load_matrix_sync(bh, pBh + ko * WM_LDB + cn, WM_LDB);
                wmma::load_matrix_sync(bl, pBl + ko * WM_LDB + cn, WM_LDB);
#pragma unroll
                for (int mi = 0; mi < 2; mi++) {
                    wmma::mma_sync(c[mi][ni], ah[mi], bh, c[mi][ni]);
                    wmma::mma_sync(c[mi][ni], ah[mi], bl, c[mi][ni]);
                    wmma::mma_sync(c[mi][ni], al[mi], bh, c[mi][ni]);
                }
            }
        }
        __syncthreads();
    }

#pragma unroll
    for (int mi = 0; mi < 2; mi++)
#pragma unroll
        for (int ni = 0; ni < 4; ni++) {
            int r = i0 + mw * 32 + mi * 16;
            int cn = j0 + nw * 64 + ni * 16;
            wmma::store_matrix_sync(&C[(size_t)r * HID + cn], c[mi][ni],
                                    HID, wmma::mem_row_major);
        }
}

// ---------------- fold: Y[s] = W @ Xin[2s] + Xin[2s+1] (tensor cores) ------
// acc[s][n] = sum_k Xin[2(s0+s)][k] * W[r0+n][k]  + Xin[2(s0+s)+1][r0+n]
// A tile row-major (k contig); B tile = W rows (k contig) used as col_major.
// Epilogue addend folded into accumulator initialization.
template <int WSTRIDE_, int WOFF>
__global__ void __launch_bounds__(WM_THREADS, 1)
gemm_fold_wmma(const float* __restrict__ W,
               const float* __restrict__ Xin,
               float* __restrict__ Y) {
    __shared__ uint32_t Ahi[128 * (WM_LDA / 2)], Alo[128 * (WM_LDA / 2)];
    __shared__ uint32_t Bhi[128 * (WM_LDA / 2)], Blo[128 * (WM_LDA / 2)];

    const int tid = threadIdx.x;
    const int wid = tid >> 5;
    const int s0 = blockIdx.y * 128;     // blocked-step tile
    const int j0 = blockIdx.x * 128;     // hidden-row tile
    const int mw = wid >> 1;
    const int nw = wid & 1;

    // init accumulators from Xin odd rows: element (m,n) = Xin[2(s0+m)+1][j0+n]
    wmma::fragment<wmma::accumulator, 16, 16, 16, float> c[2][4];
#pragma unroll
    for (int mi = 0; mi < 2; mi++)
#pragma unroll
        for (int ni = 0; ni < 4; ni++) {
            const float* p0 = &Xin[(size_t)(2 * (s0 + mw * 32 + mi * 16) + 1) * HID
                                   + j0 + nw * 64 + ni * 16];
            wmma::load_matrix_sync(c[mi][ni], p0, 2 * HID, wmma::mem_row_major);
        }

    const __nv_bfloat16* pAh = (const __nv_bfloat16*)Ahi;
    const __nv_bfloat16* pAl = (const __nv_bfloat16*)Alo;
    const __nv_bfloat16* pBh = (const __nv_bfloat16*)Bhi;
    const __nv_bfloat16* pBl = (const __nv_bfloat16*)Blo;

    for (int kb = 0; kb < HID / 32; kb++) {
        const int kk = kb * 32;

        // A tile: Xin[2(s0+row)][kk + 2kp..], k contiguous
#pragma unroll
        for (int i = 0; i < 8; i++) {
            int p = tid + i * WM_THREADS;
            int row = p >> 4;
            int kp = p & 15;
            float2 a = *(const float2*)&Xin[(size_t)(2 * (s0 + row)) * HID + kk + 2 * kp];
            uint32_t hip, lop;
            bf16_split(a.x, a.y, hip, lop);
            Ahi[row * (WM_LDA / 2) + kp] = hip;
            Alo[row * (WM_LDA / 2) + kp] = lop;
        }
        // B tile: W[j0+row][WOFF + kk + 2kp..], k contiguous (col_major use)
#pragma unroll
        for (int i = 0; i < 8; i++) {
            int p = tid + i * WM_THREADS;
            int row = p >> 4;
            int kp = p & 15;
            float2 b = *(const float2*)&W[(size_t)(j0 + row) * WSTRIDE_ + WOFF + kk + 2 * kp];
            uint32_t hip, lop;
            bf16_split(b.x, b.y, hip, lop);
            Bhi[row * (WM_LDA / 2) + kp] = hip;
            Blo[row * (WM_LDA / 2) + kp] = lop;
        }
        __syncthreads();

#pragma unroll
        for (int ks = 0; ks < 2; ks++) {
            const int ko = ks * 16;
            wmma::fragment<wmma::matrix_a, 16, 16, 16, __nv_bfloat16, wmma::row_major> ah[2], al[2];
#pragma unroll
            for (int mi = 0; mi < 2; mi++) {
                int r = mw * 32 + mi * 16;
                wmma::load_matrix_sync(ah[mi], pAh + r * WM_LDA + ko, WM_LDA);
                wmma::load_matrix_sync(al[mi], pAl + r * WM_LDA + ko, WM_LDA);
            }
#pragma unroll
            for (int ni = 0; ni < 4; ni++) {
                int cn = nw * 64 + ni * 16;
                wmma::fragment<wmma::matrix_b, 16, 16, 16, __nv_bfloat16, wmma::col_major> bh, bl;
                wmma::load_matrix_sync(bh, pBh + cn * WM_LDA + ko, WM_LDA);
                wmma::load_matrix_sync(bl, pBl + cn * WM_LDA + ko, WM_LDA);
#pragma unroll
                for (int mi = 0; mi < 2; mi++) {
                    wmma::mma_sync(c[mi][ni], ah[mi], bh, c[mi][ni]);
                    wmma::mma_sync(c[mi][ni], ah[mi], bl, c[mi][ni]);
                    wmma::mma_sync(c[mi][ni], al[mi], bh, c[mi][ni]);
                }
            }
        }
        __syncthreads();
    }

#pragma unroll
    for (int mi = 0; mi < 2; mi++)
#pragma unroll
        for (int ni = 0; ni < 4; ni++) {
            int s = s0 + mw * 32 + mi * 16;
            int cn = j0 + nw * 64 + ni * 16;
            wmma::store_matrix_sync(&Y[(size_t)s * HID + cn], c[mi][ni],
                                    HID, wmma::mem_row_major);
        }
}

// ---------------- persistent recurrence kernel (256 steps, W8/X8) ---------
#define ROWS_PER_CTA (HID / NCTA)  // 16
#define RTHREADS 512

__global__ void __launch_bounds__(RTHREADS, 1)
rnn_kernel(const float* __restrict__ Wh2o,
           const float* __restrict__ bh2o,
           float* __restrict__ out) {
    __shared__ __align__(16) float sh[HID];
    __shared__ float sred[64];

    const int tid = threadIdx.x;
    const int cta = blockIdx.x;
    const int r0  = cta * ROWS_PER_CTA;
    const int repl = cta & (NREP - 1);

    const int w = tid >> 5, l = tid & 31;
    const int grp = w & 3;
    const int q   = w >> 2;

    unsigned long long Wr[4][8];
#pragma unroll
    for (int rr = 0; rr < 4; rr++)
#pragma unroll
        for (int k = 0; k < 4; k++) {
            float4 wv = *(const float4*)&g_W8[
                (size_t)(r0 + 4 * grp + rr) * HID
                + (q << 9) + (l << 2) + (k << 7)];
            Wr[rr][2 * k]     = pack2(wv.x, wv.y);
            Wr[rr][2 * k + 1] = pack2(wv.z, wv.w);
        }

    for (int t = 0; t < SEQ8; t++) {
        float xv = 0.f;
        if (tid < ROWS_PER_CTA) xv = __ldcg(&g_X8[(size_t)t * HID + r0 + tid]);

        if (t > 0) {
            if (w == 0) {
                const unsigned tgt = (unsigned)t << 7;
                unsigned e;
                do { e = ld_relaxed(&g_cnt); }
                while (__any_sync(0xffffffffu, e < tgt));
                fence_acq();
            }
            __syncthreads();

            const float* hprev = g_hrep[(t - 1) & 1][repl];
            float4 ch = __ldcg((const float4*)&hprev[(w << 7) + (l << 2)]);
            *(float4*)&sh[(w << 7) + (l << 2)] = ch;
            __syncthreads();

            const float4* sh4 = (const float4*)sh;
            unsigned long long acc2[4];
#pragma unroll
            for (int rr = 0; rr < 4; rr++) acc2[rr] = 0ull;

#pragma unroll
            for (int k = 0; k < 4; k++) {
                float4 hv = sh4[(q << 7) + (k << 5) + l];
                unsigned long long h0 = pack2(hv.x, hv.y);
                unsigned long long h1 = pack2(hv.z, hv.w);
#pragma unroll
                for (int rr = 0; rr < 4; rr++) {
                    ffma2(acc2[rr], Wr[rr][2 * k],     h0);
                    ffma2(acc2[rr], Wr[rr][2 * k + 1], h1);
                }
            }

#pragma unroll
            for (int rr = 0; rr < 4; rr++) {
                float lo, hi;
                unpack2(lo, hi, acc2[rr]);
                float v = lo + hi;
                v += __shfl_xor_sync(0xffffffffu, v, 16);
                v += __shfl_xor_sync(0xffffffffu, v, 8);
                v += __shfl_xor_sync(0xffffffffu, v, 4);
                v += __shfl_xor_sync(0xffffffffu, v, 2);
                v += __shfl_xor_sync(0xffffffffu, v, 1);
                if (l == 0) sred[w * 4 + rr] = v;
            }
            __syncthreads();

            if (tid < ROWS_PER_CTA) {
                int g = tid >> 2, rr = tid & 3;
                float v = xv;
#pragma unroll
                for (int qq = 0; qq < 4; qq++)
                    v += sred[((qq << 2) | g) * 4 + rr];
#pragma unroll
                for (int r = 0; r < NREP; r++)
                    g_hrep[t & 1][r][r0 + tid] = v;
            }
        } else {
            if (tid < ROWS_PER_CTA) {
#pragma unroll
                for (int r = 0; r < NREP; r++)
                    g_hrep[0][r][r0 + tid] = xv;
            }
        }

        if (w == 0) {
            __syncwarp();
            if (l == 0) red_add_release(&g_cnt, 1u);
        }
    }

    // readout
    if (cta == 0) {
        if (w == 0) {
            const unsigned tgt = (unsigned)SEQ8 << 7;
            unsigned e;
            do { e = ld_relaxed(&g_cnt); }
            while (__any_sync(0xffffffffu, e < tgt));
            fence_acq();
        }
        __syncthreads();
        const float* hf = g_hrep[(SEQ8 - 1) & 1][0];
        float s = 0.f;
        for (int j = tid; j < HID; j += RTHREADS) s += __ldcg(&hf[j]) * Wh2o[j];
#pragma unroll
        for (int o = 16; o > 0; o >>= 1) s += __shfl_xor_sync(0xffffffffu, s, o);
        __syncthreads();
        if (l == 0) sred[w] = s;
        __syncthreads();
        if (tid == 0) {
            float tot = 0.f;
#pragma unroll
            for (int i = 0; i < RTHREADS / 32; i++) tot += sred[i];
            tot += bh2o[0];
            out[0] = 1.f / (1.f + expf(-tot));
        }
    }
}

// ---------------- launch: fork/join two GEMM chains ------------------------
extern "C" void kernel_launch(void* const* d_in, const int* in_sizes, int n_in,
                              void* d_out, int out_size) {
    const int*   toks = (const int*)d_in[0];
    const float* emb  = (const float*)d_in[1];
    const float* Wi2h = (const float*)d_in[2];
    const float* bi2h = (const float*)d_in[3];
    const float* Wh2o = (const float*)d_in[4];
    const float* bh2o = (const float*)d_in[5];
    float* out = (float*)d_out;

    float* gX;  cudaGetSymbolAddress((void**)&gX,  g_X);
    float* gX2; cudaGetSymbolAddress((void**)&gX2, g_X2);
    float* gX4; cudaGetSymbolAddress((void**)&gX4, g_X4);
    float* gX8; cudaGetSymbolAddress((void**)&gX8, g_X8);
    float* gW2; cudaGetSymbolAddress((void**)&gW2, g_W2);
    float* gW4; cudaGetSymbolAddress((void**)&gW4, g_W4);
    float* gW8; cudaGetSymbolAddress((void**)&gW8, g_W8);

    // Side stream + events (host objects only; see R13 note on lifetime).
    cudaStream_t sB;
    cudaStreamCreateWithFlags(&sB, cudaStreamNonBlocking);
    cudaEvent_t eFork, eW2, eW4, eX8;
    cudaEventCreateWithFlags(&eFork, cudaEventDisableTiming);
    cudaEventCreateWithFlags(&eW2,   cudaEventDisableTiming);
    cudaEventCreateWithFlags(&eW4,   cudaEventDisableTiming);
    cudaEventCreateWithFlags(&eX8,   cudaEventDisableTiming);

    const dim3 wmGrid(HID / 128, HID / 128);   // 16 x 16

    // ---- main stream (0): prologue, then W-chain (WMMA tensor cores) ----
    reset_kernel<<<1, 32>>>();
    detect_tok_kernel<<<1, 256>>>(toks);
    cudaEventRecord(eFork, 0);

    // ---- side stream: X-chain ------------------------------------------
    cudaStreamWaitEvent(sB, eFork, 0);
    gemm_x_kernel<<<dim3(HID / BN, SEQ / BM), GTHREADS, 0, sB>>>(toks, emb, Wi2h, bi2h);
    gemm_fold_wmma<WSTRIDE, EMB><<<dim3(HID / 128, SEQ2 / 128), WM_THREADS, 0, sB>>>(Wi2h, gX, gX2);

    // ---- main stream: W2, W4, W8 on WMMA --------------------------------
    gemm_sq_wmma<WSTRIDE, EMB><<<wmGrid, WM_THREADS>>>(Wi2h, gW2);
    cudaEventRecord(eW2, 0);
    gemm_sq_wmma<HID, 0><<<wmGrid, WM_THREADS>>>(gW2, gW4);
    cudaEventRecord(eW4, 0);
    gemm_sq_wmma<HID, 0><<<wmGrid, WM_THREADS>>>(gW4, gW8);

    // ---- side stream: X4 (needs W2), X8 (needs W4), join ----------------
    cudaStreamWaitEvent(sB, eW2, 0);
    gemm_fold_wmma<HID, 0><<<dim3(HID / 128, SEQ4 / 128), WM_THREADS, 0, sB>>>(gW2, gX2, gX4);
    cudaStreamWaitEvent(sB, eW4, 0);
    gemm_fold_wmma<HID, 0><<<dim3(HID / 128, SEQ8 / 128), WM_THREADS, 0, sB>>>(gW4, gX4, gX8);
    cudaEventRecord(eX8, sB);

    // ---- main stream: recurrence after W8 (order) + X8 (event) ---------
    cudaStreamWaitEvent(0, eX8, 0);
    rnn_kernel<<<NCTA, RTHREADS>>>(Wh2o, bh2o, out);
}

// round 17
// speedup vs baseline: 4.1758x; 1.0444x over previous
#include <cuda_runtime.h>
#include <cuda_bf16.h>
#include <mma.h>
#include <math.h>
#include <stdint.h>

using namespace nvcuda;

#define SEQ   2048
#define SEQ2  (SEQ / 2)
#define SEQ4  (SEQ / 4)
#define SEQ8  (SEQ / 8)
#define SEQ16 (SEQ / 16)      // 128 blocked-16 steps
#define EMB   1024
#define HID   2048
#define VOCAB 50257
#define WSTRIDE (EMB + HID)   // 3072, row stride of W_i2h

#define NCTA 128
#define NREP 4

// ---------------- scratch (device globals: allocation-free rule) ----------
__device__ __align__(16) float g_X  [SEQ   * HID];
__device__ __align__(16) float g_X2 [SEQ2  * HID];
__device__ __align__(16) float g_X4 [SEQ4  * HID];
__device__ __align__(16) float g_X8 [SEQ8  * HID];
__device__ __align__(16) float g_X16[SEQ16 * HID];
__device__ __align__(16) float g_W2 [HID * HID];
__device__ __align__(16) float g_W4 [HID * HID];
__device__ __align__(16) float g_W8 [HID * HID];
__device__ __align__(16) float g_W16[HID * HID];
// bf16 hi/lo copies, stored as packed bf16x2 words
__device__ __align__(16) uint32_t g_Whh [HID * HID / 2], g_Whl [HID * HID / 2];
__device__ __align__(16) uint32_t g_W2h [HID * HID / 2], g_W2l [HID * HID / 2];
__device__ __align__(16) uint32_t g_W4h [HID * HID / 2], g_W4l [HID * HID / 2];
__device__ __align__(16) uint32_t g_W8h [HID * HID / 2], g_W8l [HID * HID / 2];
__device__ __align__(16) uint32_t g_Xh  [SEQ  * HID / 2], g_Xl  [SEQ  * HID / 2];
__device__ __align__(16) uint32_t g_X2h [SEQ2 * HID / 2], g_X2l [SEQ2 * HID / 2];
__device__ __align__(16) uint32_t g_X4h [SEQ4 * HID / 2], g_X4l [SEQ4 * HID / 2];
__device__ __align__(16) uint32_t g_X8h [SEQ8 * HID / 2], g_X8l [SEQ8 * HID / 2];
__device__ __align__(16) float g_hrep[2][NREP][HID];
__device__ unsigned g_cnt;
__device__ int g_tok64 = 0;

// ---------------- memory-order / packed-math helpers ----------------------
__device__ __forceinline__ unsigned ld_relaxed(const unsigned* p) {
    unsigned v;
    asm volatile("ld.relaxed.gpu.global.u32 %0, [%1];" : "=r"(v) : "l"(p) : "memory");
    return v;
}
__device__ __forceinline__ void red_add_release(unsigned* p, unsigned v) {
    asm volatile("red.release.gpu.global.add.u32 [%0], %1;" :: "l"(p), "r"(v) : "memory");
}
__device__ __forceinline__ void fence_acq() {
    asm volatile("fence.acq_rel.gpu;" ::: "memory");
}
__device__ __forceinline__ unsigned long long pack2(float lo, float hi) {
    unsigned long long r;
    asm("mov.b64 %0, {%1, %2};" : "=l"(r) : "f"(lo), "f"(hi));
    return r;
}
__device__ __forceinline__ void unpack2(float& lo, float& hi, unsigned long long v) {
    asm("mov.b64 {%0, %1}, %2;" : "=f"(lo), "=f"(hi) : "l"(v));
}
__device__ __forceinline__ void ffma2(unsigned long long& acc,
                                      unsigned long long a, unsigned long long b) {
    asm("fma.rn.f32x2 %0, %1, %2, %0;" : "+l"(acc) : "l"(a), "l"(b));
}

// bf16 hi/lo split of two floats, packed as bf16x2 words (x0 in low 16)
__device__ __forceinline__ void bf16_split(float x0, float x1,
                                           uint32_t& hip, uint32_t& lop) {
    uint32_t b0 = __float_as_uint(x0), b1 = __float_as_uint(x1);
    hip = (b1 & 0xFFFF0000u) | (b0 >> 16);          // truncation split
    float l0 = x0 - __uint_as_float(b0 & 0xFFFF0000u);
    float l1 = x1 - __uint_as_float(b1 & 0xFFFF0000u);
    asm("cvt.rn.satfinite.bf16x2.f32 %0, %1, %2;" : "=r"(lop) : "f"(l1), "f"(l0));
}

// ---------------- per-launch reset ----------------------------------------
__global__ void reset_kernel() {
    if (threadIdx.x == 0) g_cnt = 0;
}

// ---------------- token dtype detection -----------------------------------
__global__ void detect_tok_kernel(const int* __restrict__ p) {
    __shared__ int bad;
    if (threadIdx.x == 0) bad = 0;
    __syncthreads();
    int mybad = 0;
    for (int i = threadIdx.x; i < SEQ / 2; i += blockDim.x) {
        int lo = p[2 * i];
        int hi = p[2 * i + 1];
        if (hi != 0 || lo < 0 || lo >= VOCAB) mybad = 1;
    }
    if (mybad) atomicOr(&bad, 1);
    __syncthreads();
    if (threadIdx.x == 0) g_tok64 = bad ? 0 : 1;
}

// ---------------- fp32 -> hi/lo bf16 convert (strided source view) --------
template <int SSTRIDE, int SOFF>
__global__ void __launch_bounds__(256, 4)
convert_kernel(const float* __restrict__ src,
               uint32_t* __restrict__ h, uint32_t* __restrict__ l,
               int npairs) {       // npairs = rows * HID / 2
    int idx = blockIdx.x * 256 + threadIdx.x;
    if (idx >= npairs) return;
    int r = idx / (HID / 2);
    int cp = idx - r * (HID / 2);
    float2 v = *(const float2*)&src[(size_t)r * SSTRIDE + SOFF + 2 * cp];
    uint32_t hip, lop;
    bf16_split(v.x, v.y, hip, lop);
    h[idx] = hip;
    l[idx] = lop;
}

// =================== SIMT GEMM (X only; proven) ===========================
#define BM 128
#define BN 128
#define BK 16
#define GTHREADS 256

__global__ void __launch_bounds__(GTHREADS, 1)
gemm_x_kernel(const int* __restrict__ toks,
              const float* __restrict__ emb,
              const float* __restrict__ Wi2h,
              const float* __restrict__ bias) {
    __shared__ __align__(16) float As[BK][BM + 4];
    __shared__ __align__(16) float Bs[BK][BN + 4];
    __shared__ int stok[BM];

    const int tid = threadIdx.x;
    const int t0 = blockIdx.y * BM;
    const int r0 = blockIdx.x * BN;
    const int tok64 = g_tok64;

    if (tid < BM) {
        int t = t0 + tid;
        stok[tid] = tok64 ? toks[2 * t] : toks[t];
    }
    __syncthreads();

    const int tx = tid & 15;
    const int ty = tid >> 4;

    float acc[8][8];
#pragma unroll
    for (int i = 0; i < 8; i++)
#pragma unroll
        for (int j = 0; j < 8; j++) acc[i][j] = 0.f;

    for (int kk = 0; kk < EMB; kk += BK) {
#pragma unroll
        for (int i = 0; i < 2; i++) {
            int v = tid + i * GTHREADS;
            int m = v >> 2;
            int k = (v & 3) << 2;
            float4 a = *(const float4*)&emb[(size_t)stok[m] * EMB + kk + k];
            As[k + 0][m] = a.x; As[k + 1][m] = a.y;
            As[k + 2][m] = a.z; As[k + 3][m] = a.w;
            float4 b = *(const float4*)&Wi2h[(size_t)(r0 + m) * WSTRIDE + kk + k];
            Bs[k + 0][m] = b.x; Bs[k + 1][m] = b.y;
            Bs[k + 2][m] = b.z; Bs[k + 3][m] = b.w;
        }
        __syncthreads();
#pragma unroll
        for (int k = 0; k < BK; k++) {
            float a[8], b[8];
            *(float4*)&a[0] = *(const float4*)&As[k][ty * 8];
            *(float4*)&a[4] = *(const float4*)&As[k][ty * 8 + 4];
            *(float4*)&b[0] = *(const float4*)&Bs[k][tx * 8];
            *(float4*)&b[4] = *(const float4*)&Bs[k][tx * 8 + 4];
#pragma unroll
            for (int i = 0; i < 8; i++)
#pragma unroll
                for (int j = 0; j < 8; j++) acc[i][j] += a[i] * b[j];
        }
        __syncthreads();
    }

    float bv[8];
#pragma unroll
    for (int j = 0; j < 8; j++) bv[j] = bias[r0 + tx * 8 + j];

#pragma unroll
    for (int i = 0; i < 8; i++) {
        int t = t0 + ty * 8 + i;
        float o[8];
#pragma unroll
        for (int j = 0; j < 8; j++) o[j] = acc[i][j] + bv[j];
        *(float4*)&g_X[(size_t)t * HID + r0 + tx * 8]     = *(float4*)&o[0];
        *(float4*)&g_X[(size_t)t * HID + r0 + tx * 8 + 4] = *(float4*)&o[4];
    }
}

// =================== WMMA bf16x3 kernels (bf16 operands in GMEM) ==========
#define WM_LDA 40               // bf16 elems per A-style tile row
#define WM_LDB 136              // bf16 elems per B-style (n-contig) row
#define WM_THREADS 256

// ---------------- square product: C(fp32) = A @ A, A given as hi/lo -------
__global__ void __launch_bounds__(WM_THREADS, 1)
gemm_sq_wmma(const uint32_t* __restrict__ Ah32, const uint32_t* __restrict__ Al32,
             float* __restrict__ C) {
    __shared__ uint32_t Ahi[128 * (WM_LDA / 2)], Alo[128 * (WM_LDA / 2)];
    __shared__ uint32_t Bhi[32 * (WM_LDB / 2)],  Blo[32 * (WM_LDB / 2)];

    const int tid = threadIdx.x;
    const int wid = tid >> 5;
    const int i0 = blockIdx.y * 128;
    const int j0 = blockIdx.x * 128;
    const int mw = wid >> 1;
    const int nw = wid & 1;

    const __nv_bfloat16* gAh = (const __nv_bfloat16*)Ah32;
    const __nv_bfloat16* gAl = (const __nv_bfloat16*)Al32;

    wmma::fragment<wmma::accumulator, 16, 16, 16, float> c[2][4];
#pragma unroll
    for (int mi = 0; mi < 2; mi++)
#pragma unroll
        for (int ni = 0; ni < 4; ni++) wmma::fill_fragment(c[mi][ni], 0.f);

    const __nv_bfloat16* pAh = (const __nv_bfloat16*)Ahi;
    const __nv_bfloat16* pAl = (const __nv_bfloat16*)Alo;
    const __nv_bfloat16* pBh = (const __nv_bfloat16*)Bhi;
    const __nv_bfloat16* pBl = (const __nv_bfloat16*)Blo;

    for (int kb = 0; kb < HID / 32; kb++) {
        const int kk = kb * 32;

#pragma unroll
        for (int i = 0; i < 2; i++) {
            int p = tid + i * WM_THREADS;
            int row = p >> 2;
            int q = p & 3;
            const uint4* shh = (const uint4*)&gAh[(size_t)(i0 + row) * HID + kk];
            const uint4* sll = (const uint4*)&gAl[(size_t)(i0 + row) * HID + kk];
            *(uint4*)&Ahi[row * (WM_LDA / 2) + q * 4] = shh[q];
            *(uint4*)&Alo[row * (WM_LDA / 2) + q * 4] = sll[q];
        }
#pragma unroll
        for (int i = 0; i < 2; i++) {
            int p = tid + i * WM_THREADS;
            int kr = p >> 4;
            int q = p & 15;
            const uint4* shh = (const uint4*)&gAh[(size_t)(kk + kr) * HID + j0];
            const uint4* sll = (const uint4*)&gAl[(size_t)(kk + kr) * HID + j0];
            *(uint4*)&Bhi[kr * (WM_LDB / 2) + q * 4] = shh[q];
            *(uint4*)&Blo[kr * (WM_LDB / 2) + q * 4] = sll[q];
        }
        __syncthreads();

#pragma unroll
        for (int ks = 0; ks < 2; ks++) {
            const int ko = ks * 16;
            wmma::fragment<wmma::matrix_a, 16, 16, 16, __nv_bfloat16, wmma::row_major> ah[2], al[2];
#pragma unroll
            for (int mi = 0; mi < 2; mi++) {
                int r = mw * 32 + mi * 16;
                wmma::load_matrix_sync(ah[mi], pAh + r * WM_LDA + ko, WM_LDA);
                wmma::load_matrix_sync(al[mi], pAl + r * WM_LDA + ko, WM_LDA);
            }
#pragma unroll
            for (int ni = 0; ni < 4; ni++) {
                int cn = nw * 64 + ni * 16;
                wmma::fragment<wmma::matrix_b, 16, 16, 16, __nv_bfloat16, wmma::row_major> bh, bl;
                wmma::load_matrix_sync(bh, pBh + ko * WM_LDB + cn, WM_LDB);
                wmma::load_matrix_sync(bl, pBl + ko * WM_LDB + cn, WM_LDB);
#pragma unroll
                for (int mi = 0; mi < 2; mi++) {
                    wmma::mma_sync(c[mi][ni], ah[mi], bh, c[mi][ni]);
                    wmma::mma_sync(c[mi][ni], ah[mi], bl, c[mi][ni]);
                    wmma::mma_sync(c[mi][ni], al[mi], bh, c[mi][ni]);
                }
            }
        }
        __syncthreads();
    }

#pragma unroll
    for (int mi = 0; mi < 2; mi++)
#pragma unroll
        for (int ni = 0; ni < 4; ni++) {
            int r = i0 + mw * 32 + mi * 16;
            int cn = j0 + nw * 64 + ni * 16;
            wmma::store_matrix_sync(&C[(size_t)r * HID + cn], c[mi][ni],
                                    HID, wmma::mem_row_major);
        }
}

// ---------------- fold: Y[s] = W @ Xin[2s] + Xin[2s+1] --------------------
// W, Xin given as hi/lo bf16 (row-major, k-contig); addend from Xin fp32.
__global__ void __launch_bounds__(WM_THREADS, 1)
gemm_fold_wmma(const uint32_t* __restrict__ Wh32, const uint32_t* __restrict__ Wl32,
               const float* __restrict__ Xf,
               const uint32_t* __restrict__ Xh32, const uint32_t* __restrict__ Xl32,
               float* __restrict__ Y) {
    __shared__ uint32_t Ahi[128 * (WM_LDA / 2)], Alo[128 * (WM_LDA / 2)];
    __shared__ uint32_t Bhi[128 * (WM_LDA / 2)], Blo[128 * (WM_LDA / 2)];

    const int tid = threadIdx.x;
    const int wid = tid >> 5;
    const int s0 = blockIdx.y * 128;
    const int j0 = blockIdx.x * 128;
    const int mw = wid >> 1;
    const int nw = wid & 1;

    const __nv_bfloat16* gWh = (const __nv_bfloat16*)Wh32;
    const __nv_bfloat16* gWl = (const __nv_bfloat16*)Wl32;
    const __nv_bfloat16* gXh = (const __nv_bfloat16*)Xh32;
    const __nv_bfloat16* gXl = (const __nv_bfloat16*)Xl32;

    wmma::fragment<wmma::accumulator, 16, 16, 16, float> c[2][4];
#pragma unroll
    for (int mi = 0; mi < 2; mi++)
#pragma unroll
        for (int ni = 0; ni < 4; ni++) {
            const float* p0 = &Xf[(size_t)(2 * (s0 + mw * 32 + mi * 16) + 1) * HID
                                  + j0 + nw * 64 + ni * 16];
            wmma::load_matrix_sync(c[mi][ni], p0, 2 * HID, wmma::mem_row_major);
        }

    const __nv_bfloat16* pAh = (const __nv_bfloat16*)Ahi;
    const __nv_bfloat16* pAl = (const __nv_bfloat16*)Alo;
    const __nv_bfloat16* pBh = (const __nv_bfloat16*)Bhi;
    const __nv_bfloat16* pBl = (const __nv_bfloat16*)Blo;

    for (int kb = 0; kb < HID / 32; kb++) {
        const int kk = kb * 32;

#pragma unroll
        for (int i = 0; i < 2; i++) {
            int p = tid + i * WM_THREADS;
            int row = p >> 2;
            int q = p & 3;
            const uint4* shh = (const uint4*)&gXh[(size_t)(2 * (s0 + row)) * HID + kk];
            const uint4* sll = (const uint4*)&gXl[(size_t)(2 * (s0 + row)) * HID + kk];
            *(uint4*)&Ahi[row * (WM_LDA / 2) + q * 4] = shh[q];
            *(uint4*)&Alo[row * (WM_LDA / 2) + q * 4] = sll[q];
        }
#pragma unroll
        for (int i = 0; i < 2; i++) {
            int p = tid + i * WM_THREADS;
            int row = p >> 2;
            int q = p & 3;
            const uint4* shh = (const uint4*)&gWh[(size_t)(j0 + row) * HID + kk];
            const uint4* sll = (const uint4*)&gWl[(size_t)(j0 + row) * HID + kk];
            *(uint4*)&Bhi[row * (WM_LDA / 2) + q * 4] = shh[q];
            *(uint4*)&Blo[row * (WM_LDA / 2) + q * 4] = sll[q];
        }
        __syncthreads();

#pragma unroll
        for (int ks = 0; ks < 2; ks++) {
            const int ko = ks * 16;
            wmma::fragment<wmma::matrix_a, 16, 16, 16, __nv_bfloat16, wmma::row_major> ah[2], al[2];
#pragma unroll
            for (int mi = 0; mi < 2; mi++) {
                int r = mw * 32 + mi * 16;
                wmma::load_matrix_sync(ah[mi], pAh + r * WM_LDA + ko, WM_LDA);
                wmma::load_matrix_sync(al[mi], pAl + r * WM_LDA + ko, WM_LDA);
            }
#pragma unroll
            for (int ni = 0; ni < 4; ni++) {
                int cn = nw * 64 + ni * 16;
                wmma::fragment<wmma::matrix_b, 16, 16, 16, __nv_bfloat16, wmma::col_major> bh, bl;
                wmma::load_matrix_sync(bh, pBh + cn * WM_LDA + ko, WM_LDA);
                wmma::load_matrix_sync(bl, pBl + cn * WM_LDA + ko, WM_LDA);
#pragma unroll
                for (int mi = 0; mi < 2; mi++) {
                    wmma::mma_sync(c[mi][ni], ah[mi], bh, c[mi][ni]);
                    wmma::mma_sync(c[mi][ni], ah[mi], bl, c[mi][ni]);
                    wmma::mma_sync(c[mi][ni], al[mi], bh, c[mi][ni]);
                }
            }
        }
        __syncthreads();
    }

#pragma unroll
    for (int mi = 0; mi < 2; mi++)
#pragma unroll
        for (int ni = 0; ni < 4; ni++) {
            int s = s0 + mw * 32 + mi * 16;
            int cn = j0 + nw * 64 + ni * 16;
            wmma::store_matrix_sync(&Y[(size_t)s * HID + cn], c[mi][ni],
                                    HID, wmma::mem_row_major);
        }
}

// ---------------- persistent recurrence kernel (128 steps, W16/X16) -------
#define ROWS_PER_CTA (HID / NCTA)  // 16
#define RTHREADS 512

__global__ void __launch_bounds__(RTHREADS, 1)
rnn_kernel(const float* __restrict__ Wh2o,
           const float* __restrict__ bh2o,
           float* __restrict__ out) {
    __shared__ __align__(16) float sh[HID];
    __shared__ float sred[64];

    const int tid = threadIdx.x;
    const int cta = blockIdx.x;
    const int r0  = cta * ROWS_PER_CTA;
    const int repl = cta & (NREP - 1);

    const int w = tid >> 5, l = tid & 31;
    const int grp = w & 3;
    const int q   = w >> 2;

    unsigned long long Wr[4][8];
#pragma unroll
    for (int rr = 0; rr < 4; rr++)
#pragma unroll
        for (int k = 0; k < 4; k++) {
            float4 wv = *(const float4*)&g_W16[
                (size_t)(r0 + 4 * grp + rr) * HID
                + (q << 9) + (l << 2) + (k << 7)];
            Wr[rr][2 * k]     = pack2(wv.x, wv.y);
            Wr[rr][2 * k + 1] = pack2(wv.z, wv.w);
        }

    for (int t = 0; t < SEQ16; t++) {
        float xv = 0.f;
        if (tid < ROWS_PER_CTA) xv = __ldcg(&g_X16[(size_t)t * HID + r0 + tid]);

        if (t > 0) {
            if (w == 0) {
                const unsigned tgt = (unsigned)t << 7;
                unsigned e;
                do { e = ld_relaxed(&g_cnt); }
                while (__any_sync(0xffffffffu, e < tgt));
                fence_acq();
            }
            __syncthreads();

            const float* hprev = g_hrep[(t - 1) & 1][repl];
            float4 ch = __ldcg((const float4*)&hprev[(w << 7) + (l << 2)]);
            *(float4*)&sh[(w << 7) + (l << 2)] = ch;
            __syncthreads();

            const float4* sh4 = (const float4*)sh;
            unsigned long long acc2[4];
#pragma unroll
            for (int rr = 0; rr < 4; rr++) acc2[rr] = 0ull;

#pragma unroll
            for (int k = 0; k < 4; k++) {
                float4 hv = sh4[(q << 7) + (k << 5) + l];
                unsigned long long h0 = pack2(hv.x, hv.y);
                unsigned long long h1 = pack2(hv.z, hv.w);
#pragma unroll
                for (int rr = 0; rr < 4; rr++) {
                    ffma2(acc2[rr], Wr[rr][2 * k],     h0);
                    ffma2(acc2[rr], Wr[rr][2 * k + 1], h1);
                }
            }

#pragma unroll
            for (int rr = 0; rr < 4; rr++) {
                float lo, hi;
                unpack2(lo, hi, acc2[rr]);
                float v = lo + hi;
                v += __shfl_xor_sync(0xffffffffu, v, 16);
                v += __shfl_xor_sync(0xffffffffu, v, 8);
                v += __shfl_xor_sync(0xffffffffu, v, 4);
                v += __shfl_xor_sync(0xffffffffu, v, 2);
                v += __shfl_xor_sync(0xffffffffu, v, 1);
                if (l == 0) sred[w * 4 + rr] = v;
            }
            __syncthreads();

            if (tid < ROWS_PER_CTA) {
                int g = tid >> 2, rr = tid & 3;
                float v = xv;
#pragma unroll
                for (int qq = 0; qq < 4; qq++)
                    v += sred[((qq << 2) | g) * 4 + rr];
#pragma unroll
                for (int r = 0; r < NREP; r++)
                    g_hrep[t & 1][r][r0 + tid] = v;
            }
        } else {
            if (tid < ROWS_PER_CTA) {
#pragma unroll
                for (int r = 0; r < NREP; r++)
                    g_hrep[0][r][r0 + tid] = xv;
            }
        }

        if (w == 0) {
            __syncwarp();
            if (l == 0) red_add_release(&g_cnt, 1u);
        }
    }

    // readout
    if (cta == 0) {
        if (w == 0) {
            const unsigned tgt = (unsigned)SEQ16 << 7;
            unsigned e;
            do { e = ld_relaxed(&g_cnt); }
            while (__any_sync(0xffffffffu, e < tgt));
            fence_acq();
        }
        __syncthreads();
        const float* hf = g_hrep[(SEQ16 - 1) & 1][0];
        float s = 0.f;
        for (int j = tid; j < HID; j += RTHREADS) s += __ldcg(&hf[j]) * Wh2o[j];
#pragma unroll
        for (int o = 16; o > 0; o >>= 1) s += __shfl_xor_sync(0xffffffffu, s, o);
        __syncthreads();
        if (l == 0) sred[w] = s;
        __syncthreads();
        if (tid == 0) {
            float tot = 0.f;
#pragma unroll
            for (int i = 0; i < RTHREADS / 32; i++) tot += sred[i];
            tot += bh2o[0];
            out[0] = 1.f / (1.f + expf(-tot));
        }
    }
}

// ---------------- launch: fork/join two GEMM chains ------------------------
extern "C" void kernel_launch(void* const* d_in, const int* in_sizes, int n_in,
                              void* d_out, int out_size) {
    const int*   toks = (const int*)d_in[0];
    const float* emb  = (const float*)d_in[1];
    const float* Wi2h = (const float*)d_in[2];
    const float* bi2h = (const float*)d_in[3];
    const float* Wh2o = (const float*)d_in[4];
    const float* bh2o = (const float*)d_in[5];
    float* out = (float*)d_out;

    float *gX, *gX2, *gX4, *gX8, *gX16, *gW2, *gW4, *gW8, *gW16;
    cudaGetSymbolAddress((void**)&gX,   g_X);
    cudaGetSymbolAddress((void**)&gX2,  g_X2);
    cudaGetSymbolAddress((void**)&gX4,  g_X4);
    cudaGetSymbolAddress((void**)&gX8,  g_X8);
    cudaGetSymbolAddress((void**)&gX16, g_X16);
    cudaGetSymbolAddress((void**)&gW2,  g_W2);
    cudaGetSymbolAddress((void**)&gW4,  g_W4);
    cudaGetSymbolAddress((void**)&gW8,  g_W8);
    cudaGetSymbolAddress((void**)&gW16, g_W16);
    uint32_t *whh, *whl, *w2h, *w2l, *w4h, *w4l, *w8h, *w8l;
    uint32_t *xh, *xl, *x2h, *x2l, *x4h, *x4l, *x8h, *x8l;
    cudaGetSymbolAddress((void**)&whh, g_Whh); cudaGetSymbolAddress((void**)&whl, g_Whl);
    cudaGetSymbolAddress((void**)&w2h, g_W2h); cudaGetSymbolAddress((void**)&w2l, g_W2l);
    cudaGetSymbolAddress((void**)&w4h, g_W4h); cudaGetSymbolAddress((void**)&w4l, g_W4l);
    cudaGetSymbolAddress((void**)&w8h, g_W8h); cudaGetSymbolAddress((void**)&w8l, g_W8l);
    cudaGetSymbolAddress((void**)&xh,  g_Xh);  cudaGetSymbolAddress((void**)&xl,  g_Xl);
    cudaGetSymbolAddress((void**)&x2h, g_X2h); cudaGetSymbolAddress((void**)&x2l, g_X2l);
    cudaGetSymbolAddress((void**)&x4h, g_X4h); cudaGetSymbolAddress((void**)&x4l, g_X4l);
    cudaGetSymbolAddress((void**)&x8h, g_X8h); cudaGetSymbolAddress((void**)&x8l, g_X8l);

    // Side stream + events (host objects only; see earlier note on lifetime).
    cudaStream_t sB;
    cudaStreamCreateWithFlags(&sB, cudaStreamNonBlocking);
    cudaEvent_t eFork, eW2, eW4, eW8, eX16;
    cudaEventCreateWithFlags(&eFork, cudaEventDisableTiming);
    cudaEventCreateWithFlags(&eW2,   cudaEventDisableTiming);
    cudaEventCreateWithFlags(&eW4,   cudaEventDisableTiming);
    cudaEventCreateWithFlags(&eW8,   cudaEventDisableTiming);
    cudaEventCreateWithFlags(&eX16,  cudaEventDisableTiming);

    const dim3 wmGrid(HID / 128, HID / 128);
    const int CVT = 256;
    const int npW  = HID * HID / 2;
    const int npX  = SEQ * HID / 2, npX2 = SEQ2 * HID / 2;
    const int npX4 = SEQ4 * HID / 2, npX8 = SEQ8 * HID / 2;

    // ---- main stream: prologue + W hi/lo, then W-chain -------------------
    reset_kernel<<<1, 32>>>();
    detect_tok_kernel<<<1, 256>>>(toks);
    convert_kernel<WSTRIDE, EMB><<<(npW + CVT - 1) / CVT, CVT>>>(Wi2h, whh, whl, npW);
    cudaEventRecord(eFork, 0);

    // ---- side stream: X-chain --------------------------------------------
    cudaStreamWaitEvent(sB, eFork, 0);
    gemm_x_kernel<<<dim3(HID / BN, SEQ / BM), GTHREADS, 0, sB>>>(toks, emb, Wi2h, bi2h);
    convert_kernel<HID, 0><<<(npX + CVT - 1) / CVT, CVT, 0, sB>>>(gX, xh, xl, npX);
    gemm_fold_wmma<<<dim3(HID / 128, SEQ2 / 128), WM_THREADS, 0, sB>>>(whh, whl, gX, xh, xl, gX2);
    convert_kernel<HID, 0><<<(npX2 + CVT - 1) / CVT, CVT, 0, sB>>>(gX2, x2h, x2l, npX2);

    // ---- main stream: W2, W4, W8, W16 (sq + converts) ---------------------
    gemm_sq_wmma<<<wmGrid, WM_THREADS>>>(whh, whl, gW2);
    convert_kernel<HID, 0><<<(npW + CVT - 1) / CVT, CVT>>>(gW2, w2h, w2l, npW);
    cudaEventRecord(eW2, 0);
    gemm_sq_wmma<<<wmGrid, WM_THREADS>>>(w2h, w2l, gW4);
    convert_kernel<HID, 0><<<(npW + CVT - 1) / CVT, CVT>>>(gW4, w4h, w4l, npW);
    cudaEventRecord(eW4, 0);
    gemm_sq_wmma<<<wmGrid, WM_THREADS>>>(w4h, w4l, gW8);
    convert_kernel<HID, 0><<<(npW + CVT - 1) / CVT, CVT>>>(gW8, w8h, w8l, npW);
    cudaEventRecord(eW8, 0);
    gemm_sq_wmma<<<wmGrid, WM_THREADS>>>(w8h, w8l, gW16);

    // ---- side stream: X4, X8, X16 -----------------------------------------
    cudaStreamWaitEvent(sB, eW2, 0);
    gemm_fold_wmma<<<dim3(HID / 128, SEQ4 / 128), WM_THREADS, 0, sB>>>(w2h, w2l, gX2, x2h, x2l, gX4);
    convert_kernel<HID, 0><<<(npX4 + CVT - 1) / CVT, CVT, 0, sB>>>(gX4, x4h, x4l, npX4);
    cudaStreamWaitEvent(sB, eW4, 0);
    gemm_fold_wmma<<<dim3(HID / 128, SEQ8 / 128), WM_THREADS, 0, sB>>>(w4h, w4l, gX4, x4h, x4l, gX8);
    convert_kernel<HID, 0><<<(npX8 + CVT - 1) / CVT, CVT, 0, sB>>>(gX8, x8h, x8l, npX8);
    cudaStreamWaitEvent(sB, eW8, 0);
    gemm_fold_wmma<<<dim3(HID / 128, SEQ16 / 128), WM_THREADS, 0, sB>>>(w8h, w8l, gX8, x8h, x8l, gX16);
    cudaEventRecord(eX16, sB);

    // ---- main stream: recurrence after W16 (order) + X16 (event) ----------
    cudaStreamWaitEvent(0, eX16, 0);
    rnn_kernel<<<NCTA, RTHREADS>>>(Wh2o, bh2o, out);
}